// round 11
// baseline (speedup 1.0000x reference)
#include <cuda_runtime.h>
#include <cuda_fp16.h>
#include <math.h>
#include <stdint.h>

// ===========================================================================
// TxtNet, single-term fp16 HMMA.16816 (fp32 accum) fed by cp.async.bulk.
// R11 = R10 + CROSS-CHUNK fragment pipelining: the k-step LDSM prefetch never
// drains at chunk boundaries (next chunk's kstep-0 frags are loaded during the
// current chunk's last k-step), and empty-barrier arrival happens as soon as
// the buffer's last k-step is loaded. Crossbar streams concurrently with the
// tensor pipe instead of alternating. Also: dead n-subtile skip in conv tile1.
// Chunk-major pre-swizzled GMEM layouts. Conv: 4 GEMMs, K=ntap*320.
// SLP: 16384 x 1216 x 512 with the x5==x3 fold.
// ===========================================================================

#define P_TOT 16384

// conv smem: A 16K + B 20K per buffer, 5 buffers
#define CH_A 0
#define CH_B 16384
#define CH_BUF 36864
#define C_NBUF 5
#define CONV_SMEM (C_NBUF * CH_BUF + 128)
// slp smem: A 16K + B 16K per buffer, 6 buffers
#define SL_A 0
#define SL_B 16384
#define SL_BUF 32768
#define S_NBUF 6
#define SLP_SMEM (S_NBUF * SL_BUF + 128)

// ------------------------- device scratch (zero-init) ----------------------
__device__ __half g_xc[32 * 5 * 528 * 64];    // [b][kc][row 528 pad][64] sw(row&7)
__device__ __half g_wcc[65 * 320 * 64];       // [slab][oc][64] sw(oc&7)
__device__ __half g_hc[19 * 16384 * 64];      // [kc][pos][64] sw(pos&7)
__device__ __half g_wec[19 * 512 * 64];       // [kc][oc][64] sw(oc&7)
__device__ float g_bconv[1200];

__constant__ int c_off[13] = {0,  0, 1,  -1, 0, 1,  -3, -2, -1, 0, 1, 2, 3};
__constant__ int c_base[4] = {0, 1, 3, 6};
__constant__ int c_nch[4]  = {5, 10, 15, 35};
__constant__ int c_sb[4]   = {0, 5, 15, 30};

// ------------------------- asm helpers -------------------------------------
__device__ __forceinline__ uint32_t smem_u32(const void* p) {
    uint32_t a;
    asm("{ .reg .u64 t; cvta.to.shared.u64 t, %1; cvt.u32.u64 %0, t; }"
        : "=r"(a) : "l"(p));
    return a;
}
#define BULK_G2S(dst, src, bytes, mbar)                                        \
    asm volatile(                                                              \
        "cp.async.bulk.shared::cluster.global.mbarrier::complete_tx::bytes "   \
        "[%0], [%1], %2, [%3];"                                                \
        :: "r"(dst), "l"(src), "r"(bytes), "r"(mbar) : "memory")
#define MBAR_INIT(a, c) \
    asm volatile("mbarrier.init.shared.b64 [%0], %1;" :: "r"(a), "r"(c) : "memory")
#define MBAR_EXPECT_TX(a, b) \
    asm volatile("mbarrier.arrive.expect_tx.shared.b64 _, [%0], %1;" \
                 :: "r"(a), "r"(b) : "memory")
#define MBAR_ARRIVE(a) \
    asm volatile("mbarrier.arrive.shared.b64 _, [%0];" :: "r"(a) : "memory")
#define FENCE_ASYNC() \
    asm volatile("fence.proxy.async.shared::cta;" ::: "memory")
__device__ __forceinline__ void mbar_wait(uint32_t a, uint32_t ph) {
    asm volatile(
        "{\n .reg .pred P;\nW%=:\n"
        " mbarrier.try_wait.parity.acquire.cta.shared::cta.b64 P, [%0], %1, 0x989680;\n"
        " @!P bra W%=;\n}"
        :: "r"(a), "r"(ph) : "memory");
}
#define LDSM4(R, A) \
    asm volatile("ldmatrix.sync.aligned.m8n8.x4.shared.b16 {%0,%1,%2,%3}, [%4];" \
                 : "=r"((R)[0]), "=r"((R)[1]), "=r"((R)[2]), "=r"((R)[3]) : "r"(A))
#define LDSM2(R, A) \
    asm volatile("ldmatrix.sync.aligned.m8n8.x2.shared.b16 {%0,%1}, [%2];" \
                 : "=r"((R)[0]), "=r"((R)[1]) : "r"(A))

__device__ __forceinline__ void mma16816(float* d, const uint32_t* a,
                                         const uint32_t* b) {
    asm volatile(
        "mma.sync.aligned.m16n8k16.row.col.f32.f16.f16.f32 "
        "{%0,%1,%2,%3}, {%4,%5,%6,%7}, {%8,%9}, {%0,%1,%2,%3};"
        : "+f"(d[0]), "+f"(d[1]), "+f"(d[2]), "+f"(d[3])
        : "r"(a[0]), "r"(a[1]), "r"(a[2]), "r"(a[3]), "r"(b[0]), "r"(b[1]));
}

// ------------------------- prep kernels ------------------------------------
__global__ void prep_x(const float* __restrict__ x) {
    int idx = blockIdx.x * 256 + threadIdx.x;
    if (idx >= 32 * 5 * 528 * 64) return;
    int j = idx & 63;
    int rest = idx >> 6;
    int r = rest % 528; rest /= 528;
    int kc = rest % 5;
    int b = rest / 5;
    int rr = r - 8; rr = rr < 0 ? 0 : (rr > 511 ? 511 : rr);
    int c = kc * 64 + j;
    float v = (c < 300) ? x[((size_t)(b * 512 + rr)) * 300 + c] : 0.f;
    int pir = (((j >> 3) ^ (r & 7)) << 3) | (j & 7);
    g_xc[((size_t)((b * 5 + kc) * 528 + r)) * 64 + pir] = __float2half_rn(v);
}

__global__ void prep_wc(const float* __restrict__ w1, const float* __restrict__ w2,
                        const float* __restrict__ w3, const float* __restrict__ w7) {
    int idx = blockIdx.x * 256 + threadIdx.x;
    if (idx >= 65 * 320 * 64) return;
    int j = idx & 63;
    int oc = (idx >> 6) % 320;
    int s = (idx >> 6) / 320;
    int conv = (s < 5) ? 0 : (s < 15) ? 1 : (s < 30) ? 2 : 3;
    int sb = (conv == 0) ? 0 : (conv == 1) ? 5 : (conv == 2) ? 15 : 30;
    int rel = s - sb;
    int tap = rel / 5, kc = rel % 5;
    int ic = kc * 64 + j;
    float v = 0.f;
    if (oc < 300 && ic < 300) {
        if (conv == 0)      v = w1[(oc * 300 + ic)];
        else if (conv == 1) v = w2[(oc * 300 + ic) * 2 + tap];
        else if (conv == 2) v = w3[(oc * 300 + ic) * 3 + tap];
        else                v = w7[(oc * 300 + ic) * 7 + tap];
    }
    int pir = (((j >> 3) ^ (oc & 7)) << 3) | (j & 7);
    g_wcc[((size_t)(s * 320 + oc)) * 64 + pir] = __float2half_rn(v);
}

__global__ void prep_we(const float* __restrict__ slp_w,
                        const float* __restrict__ b1, const float* __restrict__ b2,
                        const float* __restrict__ b3, const float* __restrict__ b7) {
    int idx = blockIdx.x * 256 + threadIdx.x;
    if (idx < 19 * 512 * 64) {
        int j = idx & 63;
        int oc = (idx >> 6) & 511;
        int kc = idx >> 15;
        int ic = kc * 64 + j;
        float v = 0.f;
        if (ic < 600)       v = slp_w[oc * 1500 + ic];
        else if (ic < 900)  v = slp_w[oc * 1500 + ic] + slp_w[oc * 1500 + ic + 300];
        else if (ic < 1200) v = slp_w[oc * 1500 + ic + 300];
        int pir = (((j >> 3) ^ (oc & 7)) << 3) | (j & 7);
        g_wec[((size_t)(kc * 512 + oc)) * 64 + pir] = __float2half_rn(v);
    }
    if (idx < 1200) {
        int conv = idx / 300, oc = idx % 300;
        const float* b = (conv == 0) ? b1 : (conv == 1) ? b2 : (conv == 2) ? b3 : b7;
        g_bconv[idx] = b[oc];
    }
}

// ------------------------- conv GEMM kernel (BM=128, BN=160) ---------------
__global__ __launch_bounds__(512, 1)
void conv_mma_kernel() {
    extern __shared__ char sm[];
    const uint32_t smb = smem_u32(sm);
    const uint32_t mbF = smb + C_NBUF * CH_BUF;          // full barriers
    const uint32_t mbE = mbF + C_NBUF * 8;               // empty barriers
    const int tid = threadIdx.x, lane = tid & 31, wid = tid >> 5;
    const int wm = wid & 3, wn = wid >> 2;               // 4 x 4 warps
    const int quad = lane >> 2, kp2 = (lane & 3) * 2;

    const int conv = 3 - (int)(blockIdx.x >> 1);         // long convs first
    const int oc0  = (blockIdx.x & 1) * 160;
    const int pos0 = blockIdx.y * 128;
    const int bat = pos0 >> 9, l0 = pos0 & 511;
    const int nc = c_nch[conv];
    const int sbase = c_sb[conv];
    const int tb = c_base[conv];
    const bool cut = (oc0 == 160) && (wn == 3);          // cols >=304 are dead

    if (tid == 0) {
#pragma unroll
        for (int i = 0; i < C_NBUF; ++i) {
            MBAR_INIT(mbF + i * 8, 1);
            MBAR_INIT(mbE + i * 8, 16);
        }
        FENCE_ASYNC();
    }
    __syncthreads();

    float acc[2][5][4];
#pragma unroll
    for (int mt = 0; mt < 2; ++mt)
#pragma unroll
        for (int nt = 0; nt < 5; ++nt)
#pragma unroll
            for (int e = 0; e < 4; ++e) acc[mt][nt][e] = 0.f;

    auto issue = [&](int ch, int b) {  // thread 0 only
        int tap = ch / 5, kc = ch - tap * 5;
        int dlt = c_off[tb + tap];
        const char* a = (const char*)g_xc +
            ((size_t)((bat * 5 + kc) * 528 + 8 + l0 + dlt)) * 128;
        const char* bb = (const char*)g_wcc +
            ((size_t)((sbase + ch) * 320 + oc0)) * 128;
        uint32_t d = smb + b * CH_BUF;
        uint32_t m = mbF + b * 8;
        MBAR_EXPECT_TX(m, CH_BUF);
        BULK_G2S(d + CH_A, a, 16384, m);
        BULK_G2S(d + CH_B, bb, 20480, m);
    };

    if (tid == 0) {
#pragma unroll
        for (int i = 0; i < C_NBUF; ++i)
            if (i < nc) issue(i, i);
    }

    // fragment addressing
    const int hi16 = lane >> 4;
    const int sbB = (lane >> 3) & 1;
    const int rmB = lane & 7;
    const uint32_t aRow  = (uint32_t)(wm * 32 + (lane & 15)) * 128;
    const uint32_t bRow  = (uint32_t)(wn * 40 + (lane & 7) +
                                      ((lane >> 4) & 1) * 8) * 128;
    const uint32_t bRow2 = (uint32_t)(wn * 40 + 32 + (lane & 7)) * 128;

    uint32_t ah[2][2][4], bf[2][5][2];
    auto load_k = [&](uint32_t Ab, uint32_t Bb, int kk, int s, int rmA) {
        const uint32_t sA = (uint32_t)(((kk * 2 + hi16) ^ rmA) << 4);
        const uint32_t sB = (uint32_t)(((kk * 2 + sbB) ^ rmB) << 4);
        LDSM4(ah[s][0], Ab + aRow + sA);
        LDSM4(ah[s][1], Ab + aRow + 2048 + sA);
        uint32_t t4[4];
        LDSM4(t4, Bb + bRow + sB);
        bf[s][0][0] = t4[0]; bf[s][0][1] = t4[1];
        bf[s][1][0] = t4[2]; bf[s][1][1] = t4[3];
        LDSM4(t4, Bb + bRow + 2048 + sB);
        bf[s][2][0] = t4[0]; bf[s][2][1] = t4[1];
        bf[s][3][0] = t4[2]; bf[s][3][1] = t4[3];
        if (!cut) LDSM2(bf[s][4], Bb + bRow2 + sB);
    };

    auto rm_of = [&](int ch) {
        int adj = (8 + c_off[tb + ch / 5]) & 7;
        return ((lane & 15) + adj) & 7;
    };

    // consumer trackers
    int buf = 0, eph = 0;        // empty-wait tracker (producer side, tid0)
    int fbuf = 0, fph = 0;       // full-wait tracker (consumer side)
    mbar_wait(mbF + fbuf * 8, fph);
    if (++fbuf == C_NBUF) { fbuf = 0; fph ^= 1; }
    int rmA_c = rm_of(0);
    load_k(smb + CH_A, smb + CH_B, 0, 0, rmA_c);
    int slot = 0;

    for (int ch = 0; ch < nc; ++ch) {
        const uint32_t Ab = smb + buf * CH_BUF + CH_A;
        const uint32_t Bb = smb + buf * CH_BUF + CH_B;
#pragma unroll
        for (int kk = 0; kk < 4; ++kk) {
            const int nxt = slot ^ 1;
            if (kk < 3) {
                load_k(Ab, Bb, kk + 1, nxt, rmA_c);
            } else if (ch + 1 < nc) {
                mbar_wait(mbF + fbuf * 8, fph);
                if (++fbuf == C_NBUF) { fbuf = 0; fph ^= 1; }
                int nb = (buf + 1 == C_NBUF) ? 0 : buf + 1;
                int rmn = rm_of(ch + 1);
                load_k(smb + nb * CH_BUF + CH_A, smb + nb * CH_BUF + CH_B,
                       0, nxt, rmn);
                rmA_c = rmn;
            }
            if (kk == 2 && lane == 0) MBAR_ARRIVE(mbE + buf * 8);
#pragma unroll
            for (int nt = 0; nt < 5; ++nt) {
                if (cut && nt >= 3) break;
#pragma unroll
                for (int mt = 0; mt < 2; ++mt)
                    mma16816(acc[mt][nt], ah[slot][mt], bf[slot][nt]);
            }
            slot = nxt;
        }
        if (tid == 0 && ch + C_NBUF < nc) {
            mbar_wait(mbE + buf * 8, eph);               // all 16 warps done
            issue(ch + C_NBUF, buf);
        }
        if (++buf == C_NBUF) { buf = 0; eph ^= 1; }
    }

    // epilogue: tanh(acc + bias) -> chunked+swizzled fp16 h
#pragma unroll
    for (int mt = 0; mt < 2; ++mt) {
        int r0 = pos0 + wm * 32 + mt * 16 + quad;
#pragma unroll
        for (int nt = 0; nt < 5; ++nt) {
            int col = oc0 + wn * 40 + nt * 8 + kp2;
            if (col >= 300) continue;
            int gc = conv * 300 + col;
            int kc = gc >> 6, j = gc & 63;
            float bi0 = g_bconv[gc], bi1 = g_bconv[gc + 1];
#pragma unroll
            for (int half = 0; half < 2; ++half) {
                int r = r0 + half * 8;
                __half2 hv;
                hv.x = __float2half_rn(tanhf(acc[mt][nt][half * 2 + 0] + bi0));
                hv.y = __float2half_rn(tanhf(acc[mt][nt][half * 2 + 1] + bi1));
                int pir = (((j >> 3) ^ (r & 7)) << 3) | (j & 7);
                *(__half2*)(g_hc + ((size_t)kc * 16384 + r) * 64 + pir) = hv;
            }
        }
    }
}

// ------------------------- SLP GEMM kernel (BM=128, BN=128) ----------------
__global__ __launch_bounds__(512, 1)
void slp_mma_kernel(const float* __restrict__ slp_b, float* __restrict__ out) {
    extern __shared__ char sm[];
    const uint32_t smb = smem_u32(sm);
    const uint32_t mbF = smb + S_NBUF * SL_BUF;
    const uint32_t mbE = mbF + S_NBUF * 8;
    const int tid = threadIdx.x, lane = tid & 31, wid = tid >> 5;
    const int wm = wid & 3, wn = wid >> 2;
    const int quad = lane >> 2, kp2 = (lane & 3) * 2;
    const int oc0  = blockIdx.x * 128;
    const int pos0 = blockIdx.y * 128;
    const int nc = 19;
    const int rmA = lane & 7;

    if (tid == 0) {
#pragma unroll
        for (int i = 0; i < S_NBUF; ++i) {
            MBAR_INIT(mbF + i * 8, 1);
            MBAR_INIT(mbE + i * 8, 16);
        }
        FENCE_ASYNC();
    }
    __syncthreads();

    float acc[2][4][4];
#pragma unroll
    for (int mt = 0; mt < 2; ++mt)
#pragma unroll
        for (int nt = 0; nt < 4; ++nt)
#pragma unroll
            for (int e = 0; e < 4; ++e) acc[mt][nt][e] = 0.f;

    auto issue = [&](int ch, int b) {
        const char* a = (const char*)g_hc + ((size_t)ch * 16384 + pos0) * 128;
        const char* bb = (const char*)g_wec + ((size_t)ch * 512 + oc0) * 128;
        uint32_t d = smb + b * SL_BUF;
        uint32_t m = mbF + b * 8;
        MBAR_EXPECT_TX(m, SL_BUF);
        BULK_G2S(d + SL_A, a, 16384, m);
        BULK_G2S(d + SL_B, bb, 16384, m);
    };

    if (tid == 0) {
#pragma unroll
        for (int i = 0; i < S_NBUF; ++i)
            if (i < nc) issue(i, i);
    }

    const int hi16 = lane >> 4;
    const int sbB = (lane >> 3) & 1;
    const int rmB = lane & 7;
    const uint32_t aRow  = (uint32_t)(wm * 32 + (lane & 15)) * 128;
    const uint32_t bRow  = (uint32_t)(wn * 32 + (lane & 7) +
                                      ((lane >> 4) & 1) * 8) * 128;

    uint32_t ah[2][2][4], bf[2][4][2];
    auto load_k = [&](uint32_t Ab, uint32_t Bb, int kk, int s) {
        const uint32_t sA = (uint32_t)(((kk * 2 + hi16) ^ rmA) << 4);
        const uint32_t sB = (uint32_t)(((kk * 2 + sbB) ^ rmB) << 4);
        LDSM4(ah[s][0], Ab + aRow + sA);
        LDSM4(ah[s][1], Ab + aRow + 2048 + sA);
        uint32_t t4[4];
        LDSM4(t4, Bb + bRow + sB);
        bf[s][0][0] = t4[0]; bf[s][0][1] = t4[1];
        bf[s][1][0] = t4[2]; bf[s][1][1] = t4[3];
        LDSM4(t4, Bb + bRow + 2048 + sB);
        bf[s][2][0] = t4[0]; bf[s][2][1] = t4[1];
        bf[s][3][0] = t4[2]; bf[s][3][1] = t4[3];
    };

    int buf = 0, eph = 0;
    int fbuf = 0, fph = 0;
    mbar_wait(mbF + fbuf * 8, fph);
    if (++fbuf == S_NBUF) { fbuf = 0; fph ^= 1; }
    load_k(smb + SL_A, smb + SL_B, 0, 0);
    int slot = 0;

    for (int ch = 0; ch < nc; ++ch) {
        const uint32_t Ab = smb + buf * SL_BUF + SL_A;
        const uint32_t Bb = smb + buf * SL_BUF + SL_B;
#pragma unroll
        for (int kk = 0; kk < 4; ++kk) {
            const int nxt = slot ^ 1;
            if (kk < 3) {
                load_k(Ab, Bb, kk + 1, nxt);
            } else if (ch + 1 < nc) {
                mbar_wait(mbF + fbuf * 8, fph);
                if (++fbuf == S_NBUF) { fbuf = 0; fph ^= 1; }
                int nb = (buf + 1 == S_NBUF) ? 0 : buf + 1;
                load_k(smb + nb * SL_BUF + SL_A, smb + nb * SL_BUF + SL_B,
                       0, nxt);
            }
            if (kk == 2 && lane == 0) MBAR_ARRIVE(mbE + buf * 8);
#pragma unroll
            for (int nt = 0; nt < 4; ++nt)
#pragma unroll
                for (int mt = 0; mt < 2; ++mt)
                    mma16816(acc[mt][nt], ah[slot][mt], bf[slot][nt]);
            slot = nxt;
        }
        if (tid == 0 && ch + S_NBUF < nc) {
            mbar_wait(mbE + buf * 8, eph);
            issue(ch + S_NBUF, buf);
        }
        if (++buf == S_NBUF) { buf = 0; eph ^= 1; }
    }

#pragma unroll
    for (int mt = 0; mt < 2; ++mt) {
        int r0 = pos0 + wm * 32 + mt * 16 + quad;
#pragma unroll
        for (int nt = 0; nt < 4; ++nt) {
            int col = oc0 + wn * 32 + nt * 8 + kp2;
            float bi0 = slp_b[col], bi1 = slp_b[col + 1];
#pragma unroll
            for (int half = 0; half < 2; ++half) {
                int r = r0 + half * 8;
                float2 v;
                v.x = tanhf(acc[mt][nt][half * 2 + 0] + bi0);
                v.y = tanhf(acc[mt][nt][half * 2 + 1] + bi1);
                *(float2*)(out + (size_t)r * 512 + col) = v;
            }
        }
    }
}

// ------------------------- launch ------------------------------------------
extern "C" void kernel_launch(void* const* d_in, const int* in_sizes, int n_in,
                              void* d_out, int out_size) {
    const float* x     = (const float*)d_in[0];
    const float* w1    = (const float*)d_in[1];
    const float* b1    = (const float*)d_in[2];
    const float* w2    = (const float*)d_in[3];
    const float* b2    = (const float*)d_in[4];
    const float* w3    = (const float*)d_in[5];
    const float* b3    = (const float*)d_in[6];
    const float* w7    = (const float*)d_in[7];
    const float* b7    = (const float*)d_in[8];
    const float* slp_w = (const float*)d_in[9];
    const float* slp_b = (const float*)d_in[10];
    float* out = (float*)d_out;

    cudaFuncSetAttribute(conv_mma_kernel, cudaFuncAttributeMaxDynamicSharedMemorySize, CONV_SMEM);
    cudaFuncSetAttribute(slp_mma_kernel,  cudaFuncAttributeMaxDynamicSharedMemorySize, SLP_SMEM);

    prep_x<<<(32 * 5 * 528 * 64 + 255) / 256, 256>>>(x);
    prep_wc<<<(65 * 320 * 64 + 255) / 256, 256>>>(w1, w2, w3, w7);
    prep_we<<<(19 * 512 * 64 + 255) / 256, 256>>>(slp_w, b1, b2, b3, b7);

    conv_mma_kernel<<<dim3(8, 128), 512, CONV_SMEM>>>();
    slp_mma_kernel<<<dim3(4, 128), 512, SLP_SMEM>>>(slp_b, out);
}

// round 12
// speedup vs baseline: 1.0296x; 1.0296x over previous
#include <cuda_runtime.h>
#include <cuda_fp16.h>
#include <math.h>
#include <stdint.h>

// ===========================================================================
// TxtNet, single-term fp16 HMMA.16816 (fp32 accum) fed by cp.async.bulk.
// R12: (1) conv A-slab sharing — one guarded 144-row x slab per (kc) serves
// ALL taps of the conv (kc-major, tap-inner chunk order), cutting bulk traffic
// ~40%; (2) single merged prep kernel; (3) R8's 2-CTA slp kernel; conv
// compute loop = R7's measured-best (simple per-chunk LDSM->MMA).
// Conv: 4 GEMMs, K=ntap*320. SLP: 16384 x 1216 x 512 (x5==x3 fold).
// ===========================================================================

#define P_TOT 16384

// conv smem: 2 A slabs (144 rows x 128B = 18432) + 5 B tiles (20480)
#define CH_AS   0
#define CH_ASZ  18432
#define CH_BT   36864
#define CH_BSZ  20480
#define C_NB    5
#define CONV_MB (CH_BT + C_NB * CH_BSZ)          // 139264
#define CONV_SMEM (CONV_MB + 128)
// slp smem: A 16K + B 16K per buffer, 3 buffers, 2 CTAs/SM
#define SL_A 0
#define SL_B 16384
#define SL_BUF 32768
#define S_NBUF 3
#define SLP_SMEM (S_NBUF * SL_BUF + 128)

// ------------------------- device scratch (zero-init) ----------------------
__device__ __half g_xc[32 * 5 * 528 * 64];    // [b][kc][row 528 pad][64] sw(row&7)
__device__ __half g_wcc[65 * 320 * 64];       // [slab][oc][64] sw(oc&7)
__device__ __half g_hc[19 * 16384 * 64];      // [kc][pos][64] sw(pos&7)
__device__ __half g_wec[19 * 512 * 64];       // [kc][oc][64] sw(oc&7)
__device__ float g_bconv[1200];

__constant__ int c_off[13] = {0,  0, 1,  -1, 0, 1,  -3, -2, -1, 0, 1, 2, 3};
__constant__ int c_base[4] = {0, 1, 3, 6};
__constant__ int c_ntap[4] = {1, 2, 3, 7};
__constant__ int c_sb[4]   = {0, 5, 15, 30};

// ------------------------- asm helpers -------------------------------------
__device__ __forceinline__ uint32_t smem_u32(const void* p) {
    uint32_t a;
    asm("{ .reg .u64 t; cvta.to.shared.u64 t, %1; cvt.u32.u64 %0, t; }"
        : "=r"(a) : "l"(p));
    return a;
}
#define BULK_G2S(dst, src, bytes, mbar)                                        \
    asm volatile(                                                              \
        "cp.async.bulk.shared::cluster.global.mbarrier::complete_tx::bytes "   \
        "[%0], [%1], %2, [%3];"                                                \
        :: "r"(dst), "l"(src), "r"(bytes), "r"(mbar) : "memory")
#define MBAR_INIT(a, c) \
    asm volatile("mbarrier.init.shared.b64 [%0], %1;" :: "r"(a), "r"(c) : "memory")
#define MBAR_EXPECT_TX(a, b) \
    asm volatile("mbarrier.arrive.expect_tx.shared.b64 _, [%0], %1;" \
                 :: "r"(a), "r"(b) : "memory")
#define MBAR_ARRIVE(a) \
    asm volatile("mbarrier.arrive.shared.b64 _, [%0];" :: "r"(a) : "memory")
#define FENCE_ASYNC() \
    asm volatile("fence.proxy.async.shared::cta;" ::: "memory")
__device__ __forceinline__ void mbar_wait(uint32_t a, uint32_t ph) {
    asm volatile(
        "{\n .reg .pred P;\nW%=:\n"
        " mbarrier.try_wait.parity.acquire.cta.shared::cta.b64 P, [%0], %1, 0x989680;\n"
        " @!P bra W%=;\n}"
        :: "r"(a), "r"(ph) : "memory");
}
#define LDSM4(R, A) \
    asm volatile("ldmatrix.sync.aligned.m8n8.x4.shared.b16 {%0,%1,%2,%3}, [%4];" \
                 : "=r"((R)[0]), "=r"((R)[1]), "=r"((R)[2]), "=r"((R)[3]) : "r"(A))
#define LDSM2(R, A) \
    asm volatile("ldmatrix.sync.aligned.m8n8.x2.shared.b16 {%0,%1}, [%2];" \
                 : "=r"((R)[0]), "=r"((R)[1]) : "r"(A))

__device__ __forceinline__ void mma16816(float* d, const uint32_t* a,
                                         const uint32_t* b) {
    asm volatile(
        "mma.sync.aligned.m16n8k16.row.col.f32.f16.f16.f32 "
        "{%0,%1,%2,%3}, {%4,%5,%6,%7}, {%8,%9}, {%0,%1,%2,%3};"
        : "+f"(d[0]), "+f"(d[1]), "+f"(d[2]), "+f"(d[3])
        : "r"(a[0]), "r"(a[1]), "r"(a[2]), "r"(a[3]), "r"(b[0]), "r"(b[1]));
}

// ------------------------- merged prep kernel ------------------------------
#define NX  (32 * 5 * 528 * 64)
#define NWC (65 * 320 * 64)
#define NWE (19 * 512 * 64)

__global__ void prep_all(const float* __restrict__ x,
                         const float* __restrict__ w1, const float* __restrict__ w2,
                         const float* __restrict__ w3, const float* __restrict__ w7,
                         const float* __restrict__ slp_w,
                         const float* __restrict__ b1, const float* __restrict__ b2,
                         const float* __restrict__ b3, const float* __restrict__ b7) {
    int gid = blockIdx.x * 256 + threadIdx.x;
    if (gid < NX) {
        int idx = gid;
        int j = idx & 63;
        int rest = idx >> 6;
        int r = rest % 528; rest /= 528;
        int kc = rest % 5;
        int b = rest / 5;
        int rr = r - 8; rr = rr < 0 ? 0 : (rr > 511 ? 511 : rr);
        int c = kc * 64 + j;
        float v = (c < 300) ? x[((size_t)(b * 512 + rr)) * 300 + c] : 0.f;
        int pir = (((j >> 3) ^ (r & 7)) << 3) | (j & 7);
        g_xc[((size_t)((b * 5 + kc) * 528 + r)) * 64 + pir] = __float2half_rn(v);
        return;
    }
    gid -= NX;
    if (gid < NWC) {
        int idx = gid;
        int j = idx & 63;
        int oc = (idx >> 6) % 320;
        int s = (idx >> 6) / 320;
        int conv = (s < 5) ? 0 : (s < 15) ? 1 : (s < 30) ? 2 : 3;
        int sb = (conv == 0) ? 0 : (conv == 1) ? 5 : (conv == 2) ? 15 : 30;
        int rel = s - sb;
        int tap = rel / 5, kc = rel % 5;
        int ic = kc * 64 + j;
        float v = 0.f;
        if (oc < 300 && ic < 300) {
            if (conv == 0)      v = w1[(oc * 300 + ic)];
            else if (conv == 1) v = w2[(oc * 300 + ic) * 2 + tap];
            else if (conv == 2) v = w3[(oc * 300 + ic) * 3 + tap];
            else                v = w7[(oc * 300 + ic) * 7 + tap];
        }
        int pir = (((j >> 3) ^ (oc & 7)) << 3) | (j & 7);
        g_wcc[((size_t)(s * 320 + oc)) * 64 + pir] = __float2half_rn(v);
        return;
    }
    gid -= NWC;
    if (gid < NWE) {
        int idx = gid;
        int j = idx & 63;
        int oc = (idx >> 6) & 511;
        int kc = idx >> 15;
        int ic = kc * 64 + j;
        float v = 0.f;
        if (ic < 600)       v = slp_w[oc * 1500 + ic];
        else if (ic < 900)  v = slp_w[oc * 1500 + ic] + slp_w[oc * 1500 + ic + 300];
        else if (ic < 1200) v = slp_w[oc * 1500 + ic + 300];
        int pir = (((j >> 3) ^ (oc & 7)) << 3) | (j & 7);
        g_wec[((size_t)(kc * 512 + oc)) * 64 + pir] = __float2half_rn(v);
        if (idx < 1200) {
            int conv = idx / 300, occ = idx % 300;
            const float* b = (conv == 0) ? b1 : (conv == 1) ? b2
                              : (conv == 2) ? b3 : b7;
            g_bconv[idx] = b[occ];
        }
    }
}

// ------------------------- conv GEMM kernel (BM=128, BN=160) ---------------
// A-slab sharing: chunks ordered kc-major (tap inner). One 144-row slab per kc
// serves all taps at row offset (8+off). B tiles per (tap,kc) as before.
__global__ __launch_bounds__(512, 1)
void conv_mma_kernel() {
    extern __shared__ char sm[];
    const uint32_t smb = smem_u32(sm);
    const uint32_t mbFA = smb + CONV_MB;
    const uint32_t mbEA = mbFA + 2 * 8;
    const uint32_t mbFB = mbEA + 2 * 8;
    const uint32_t mbEB = mbFB + C_NB * 8;
    const int tid = threadIdx.x, lane = tid & 31, wid = tid >> 5;
    const int wm = wid & 3, wn = wid >> 2;               // 4 x 4 warps
    const int quad = lane >> 2, kp2 = (lane & 3) * 2;

    const int conv = 3 - (int)(blockIdx.x >> 1);         // long convs first
    const int oc0  = (blockIdx.x & 1) * 160;
    const int pos0 = blockIdx.y * 128;
    const int bat = pos0 >> 9, l0 = pos0 & 511;
    const int ntap = c_ntap[conv];
    const int nq = ntap * 5;
    const int sbase = c_sb[conv];
    const int tb = c_base[conv];
    const bool cut = (oc0 == 160) && (wn == 3);          // cols >=304 dead

    if (tid == 0) {
#pragma unroll
        for (int i = 0; i < 2; ++i) {
            MBAR_INIT(mbFA + i * 8, 1);
            MBAR_INIT(mbEA + i * 8, 16);
        }
#pragma unroll
        for (int i = 0; i < C_NB; ++i) {
            MBAR_INIT(mbFB + i * 8, 1);
            MBAR_INIT(mbEB + i * 8, 16);
        }
        FENCE_ASYNC();
    }
    __syncthreads();

    float acc[2][5][4];
#pragma unroll
    for (int mt = 0; mt < 2; ++mt)
#pragma unroll
        for (int nt = 0; nt < 5; ++nt)
#pragma unroll
            for (int e = 0; e < 4; ++e) acc[mt][nt][e] = 0.f;

    auto issueA = [&](int kc, int ab) {  // tid0 only
        const char* a = (const char*)g_xc +
            ((size_t)((bat * 5 + kc) * 528 + l0)) * 128;  // slab incl. guards
        uint32_t m = mbFA + ab * 8;
        MBAR_EXPECT_TX(m, CH_ASZ);
        BULK_G2S(smb + CH_AS + ab * CH_ASZ, a, CH_ASZ, m);
    };
    auto issueB = [&](int q, int bb) {   // tid0 only; q = kc*ntap + tap
        int kc = q / ntap, tap = q - kc * ntap;
        const char* b = (const char*)g_wcc +
            ((size_t)((sbase + tap * 5 + kc) * 320 + oc0)) * 128;
        uint32_t m = mbFB + bb * 8;
        MBAR_EXPECT_TX(m, CH_BSZ);
        BULK_G2S(smb + CH_BT + bb * CH_BSZ, b, CH_BSZ, m);
    };

    if (tid == 0) {
        issueA(0, 0);
        issueA(1, 1);
#pragma unroll
        for (int i = 0; i < C_NB; ++i)
            if (i < nq) issueB(i, i);
    }

    // fragment addressing (A row offset varies per tap)
    const int hi16 = lane >> 4;
    const int sbB = (lane >> 3) & 1;
    const int rmB = lane & 7;
    const uint32_t bRow  = (uint32_t)(wn * 40 + (lane & 7) +
                                      ((lane >> 4) & 1) * 8) * 128;
    const uint32_t bRow2 = (uint32_t)(wn * 40 + 32 + (lane & 7)) * 128;

    int faph = 0;                 // consumer: A full phase (per warp)
    int bb = 0, fbph = 0;         // consumer: B full ring tracker
    int ebb = 0, ebph = 0;        // producer(tid0): B empty tracker
    int eaph = 0;                 // producer(tid0): A empty phase

    for (int kc = 0; kc < 5; ++kc) {
        const int ab = kc & 1;
        mbar_wait(mbFA + ab * 8, faph);
        if (ab == 1) faph ^= 1;
        const uint32_t Ab = smb + CH_AS + ab * CH_ASZ;

        for (int tap = 0; tap < ntap; ++tap) {
            const int q = kc * ntap + tap;
            const int off = c_off[tb + tap];
            const int adj = (8 + off) & 7;
            const int rmA = ((lane & 15) + adj) & 7;
            const uint32_t aRow = (uint32_t)(8 + off + wm * 32 +
                                             (lane & 15)) * 128;

            mbar_wait(mbFB + bb * 8, fbph);
            const uint32_t Bb = smb + CH_BT + bb * CH_BSZ;

#pragma unroll
            for (int kk = 0; kk < 4; ++kk) {
                const uint32_t sA = (uint32_t)(((kk * 2 + hi16) ^ rmA) << 4);
                const uint32_t sB = (uint32_t)(((kk * 2 + sbB) ^ rmB) << 4);
                uint32_t ah[2][4];
                LDSM4(ah[0], Ab + aRow + sA);
                LDSM4(ah[1], Ab + aRow + 2048 + sA);
                uint32_t bh4[4];
                LDSM4(bh4, Bb + bRow + sB);
#pragma unroll
                for (int mt = 0; mt < 2; ++mt) {
                    mma16816(acc[mt][0], ah[mt], bh4);
                    mma16816(acc[mt][1], ah[mt], bh4 + 2);
                }
                LDSM4(bh4, Bb + bRow + 2048 + sB);
#pragma unroll
                for (int mt = 0; mt < 2; ++mt) {
                    mma16816(acc[mt][2], ah[mt], bh4);
                    mma16816(acc[mt][3], ah[mt], bh4 + 2);
                }
                if (!cut) {
                    uint32_t bh2[2];
                    LDSM2(bh2, Bb + bRow2 + sB);
#pragma unroll
                    for (int mt = 0; mt < 2; ++mt)
                        mma16816(acc[mt][4], ah[mt], bh2);
                }
            }
            __syncwarp();
            if (lane == 0) {
                MBAR_ARRIVE(mbEB + bb * 8);
                if (tap == ntap - 1) MBAR_ARRIVE(mbEA + ab * 8);
            }
            if (tid == 0) {
                if (q + C_NB < nq) {
                    mbar_wait(mbEB + ebb * 8, ebph);     // all 16 warps done
                    issueB(q + C_NB, ebb);
                    if (++ebb == C_NB) { ebb = 0; ebph ^= 1; }
                }
                if (tap == ntap - 1 && kc + 2 < 5) {
                    mbar_wait(mbEA + ab * 8, eaph);
                    issueA(kc + 2, ab);
                    if (ab == 1) eaph ^= 1;
                }
            }
            if (++bb == C_NB) { bb = 0; fbph ^= 1; }
        }
    }

    // epilogue: tanh(acc + bias) -> chunked+swizzled fp16 h
#pragma unroll
    for (int mt = 0; mt < 2; ++mt) {
        int r0 = pos0 + wm * 32 + mt * 16 + quad;
#pragma unroll
        for (int nt = 0; nt < 5; ++nt) {
            int col = oc0 + wn * 40 + nt * 8 + kp2;
            if (col >= 300) continue;
            int gc = conv * 300 + col;
            int kc = gc >> 6, j = gc & 63;
            float bi0 = g_bconv[gc], bi1 = g_bconv[gc + 1];
#pragma unroll
            for (int half = 0; half < 2; ++half) {
                int r = r0 + half * 8;
                __half2 hv;
                hv.x = __float2half_rn(tanhf(acc[mt][nt][half * 2 + 0] + bi0));
                hv.y = __float2half_rn(tanhf(acc[mt][nt][half * 2 + 1] + bi1));
                int pir = (((j >> 3) ^ (r & 7)) << 3) | (j & 7);
                *(__half2*)(g_hc + ((size_t)kc * 16384 + r) * 64 + pir) = hv;
            }
        }
    }
}

// ------------------------- SLP GEMM kernel (R8: 256 thr, 2 CTAs/SM) --------
__global__ __launch_bounds__(256, 2)
void slp_mma_kernel(const float* __restrict__ slp_b, float* __restrict__ out) {
    extern __shared__ char sm[];
    const uint32_t smb = smem_u32(sm);
    const uint32_t mbF = smb + S_NBUF * SL_BUF;
    const uint32_t mbE = mbF + S_NBUF * 8;
    const int tid = threadIdx.x, lane = tid & 31, wid = tid >> 5;
    const int wm = wid >> 2, wn = wid & 3;               // 2 x 4 warps
    const int quad = lane >> 2, kp2 = (lane & 3) * 2;
    const int oc0  = blockIdx.x * 128;
    const int pos0 = blockIdx.y * 128;
    const int nc = 19;
    const int rmA = lane & 7;

    if (tid == 0) {
#pragma unroll
        for (int i = 0; i < S_NBUF; ++i) {
            MBAR_INIT(mbF + i * 8, 1);
            MBAR_INIT(mbE + i * 8, 8);
        }
        FENCE_ASYNC();
    }
    __syncthreads();

    float acc[4][4][4];
#pragma unroll
    for (int mt = 0; mt < 4; ++mt)
#pragma unroll
        for (int nt = 0; nt < 4; ++nt)
#pragma unroll
            for (int e = 0; e < 4; ++e) acc[mt][nt][e] = 0.f;

    auto issue = [&](int ch, int buf) {
        const char* a = (const char*)g_hc + ((size_t)ch * 16384 + pos0) * 128;
        const char* b = (const char*)g_wec + ((size_t)ch * 512 + oc0) * 128;
        uint32_t d = smb + buf * SL_BUF;
        uint32_t m = mbF + buf * 8;
        MBAR_EXPECT_TX(m, SL_BUF);
        BULK_G2S(d + SL_A, a, 16384, m);
        BULK_G2S(d + SL_B, b, 16384, m);
    };

    if (tid == 0) { issue(0, 0); issue(1, 1); issue(2, 2); }

    const int hi16 = lane >> 4;
    const int sbB = (lane >> 3) & 1;
    const int rmB = lane & 7;
    const uint32_t aRow  = (uint32_t)(wm * 64 + (lane & 15)) * 128;
    const uint32_t bRow  = (uint32_t)(wn * 32 + (lane & 7) +
                                      ((lane >> 4) & 1) * 8) * 128;

    int buf = 0, ph = 0;
    for (int ch = 0; ch < nc; ++ch) {
        mbar_wait(mbF + buf * 8, (ch / S_NBUF) & 1);
        const uint32_t Ab = smb + buf * SL_BUF + SL_A;
        const uint32_t Bb = smb + buf * SL_BUF + SL_B;
#pragma unroll
        for (int kk = 0; kk < 4; ++kk) {
            const uint32_t sA = (uint32_t)(((kk * 2 + hi16) ^ rmA) << 4);
            const uint32_t sB = (uint32_t)(((kk * 2 + sbB) ^ rmB) << 4);
            uint32_t ah[4][4];
#pragma unroll
            for (int mt = 0; mt < 4; ++mt)
                LDSM4(ah[mt], Ab + aRow + mt * 2048 + sA);
#pragma unroll
            for (int p = 0; p < 2; ++p) {
                uint32_t bh[4];
                LDSM4(bh, Bb + bRow + p * 2048 + sB);
#pragma unroll
                for (int q = 0; q < 2; ++q)
#pragma unroll
                    for (int mt = 0; mt < 4; ++mt)
                        mma16816(acc[mt][p * 2 + q], ah[mt], bh + q * 2);
            }
        }
        __syncwarp();
        if (lane == 0) MBAR_ARRIVE(mbE + buf * 8);
        if (tid == 0 && ch + S_NBUF < nc) {
            mbar_wait(mbE + buf * 8, ph);
            issue(ch + S_NBUF, buf);
        }
        if (++buf == S_NBUF) { buf = 0; ph ^= 1; }
    }

#pragma unroll
    for (int mt = 0; mt < 4; ++mt) {
        int r0 = pos0 + wm * 64 + mt * 16 + quad;
#pragma unroll
        for (int nt = 0; nt < 4; ++nt) {
            int col = oc0 + wn * 32 + nt * 8 + kp2;
            float bi0 = slp_b[col], bi1 = slp_b[col + 1];
#pragma unroll
            for (int half = 0; half < 2; ++half) {
                int r = r0 + half * 8;
                float2 v;
                v.x = tanhf(acc[mt][nt][half * 2 + 0] + bi0);
                v.y = tanhf(acc[mt][nt][half * 2 + 1] + bi1);
                *(float2*)(out + (size_t)r * 512 + col) = v;
            }
        }
    }
}

// ------------------------- launch ------------------------------------------
extern "C" void kernel_launch(void* const* d_in, const int* in_sizes, int n_in,
                              void* d_out, int out_size) {
    const float* x     = (const float*)d_in[0];
    const float* w1    = (const float*)d_in[1];
    const float* b1    = (const float*)d_in[2];
    const float* w2    = (const float*)d_in[3];
    const float* b2    = (const float*)d_in[4];
    const float* w3    = (const float*)d_in[5];
    const float* b3    = (const float*)d_in[6];
    const float* w7    = (const float*)d_in[7];
    const float* b7    = (const float*)d_in[8];
    const float* slp_w = (const float*)d_in[9];
    const float* slp_b = (const float*)d_in[10];
    float* out = (float*)d_out;

    cudaFuncSetAttribute(conv_mma_kernel, cudaFuncAttributeMaxDynamicSharedMemorySize, CONV_SMEM);
    cudaFuncSetAttribute(slp_mma_kernel,  cudaFuncAttributeMaxDynamicSharedMemorySize, SLP_SMEM);

    int ntot = NX + NWC + NWE;
    prep_all<<<(ntot + 255) / 256, 256>>>(x, w1, w2, w3, w7, slp_w,
                                          b1, b2, b3, b7);

    conv_mma_kernel<<<dim3(8, 128), 512, CONV_SMEM>>>();
    slp_mma_kernel<<<dim3(4, 128), 256, SLP_SMEM>>>(slp_b, out);
}

// round 13
// speedup vs baseline: 1.0721x; 1.0414x over previous
#include <cuda_runtime.h>
#include <cuda_fp16.h>
#include <math.h>
#include <stdint.h>

// ===========================================================================
// TxtNet, single-term fp16 HMMA.16816 (fp32 accum) fed by cp.async.bulk.
// R13: best-measured composition — R7 conv loop (+dead-column cut), R8 2-CTA
// slp, and strength-reduced prep kernels (3D-grid index decomposition, no
// div/mod, half2 stores). Chunk-major pre-swizzled GMEM layouts.
// Conv: 4 GEMMs, K=ntap*320. SLP: 16384 x 1216 x 512 (x5==x3 fold).
// ===========================================================================

#define P_TOT 16384

// conv smem: A 16K + B 20K per buffer, 5 buffers
#define CH_A 0
#define CH_B 16384
#define CH_BUF 36864
#define C_NBUF 5
#define CONV_SMEM (C_NBUF * CH_BUF + 128)
// slp smem: A 16K + B 16K per buffer, 3 buffers, 2 CTAs/SM
#define SL_A 0
#define SL_B 16384
#define SL_BUF 32768
#define S_NBUF 3
#define SLP_SMEM (S_NBUF * SL_BUF + 128)

// ------------------------- device scratch (zero-init) ----------------------
__device__ __half g_xc[32 * 5 * 528 * 64];    // [b][kc][row 528 pad][64] sw(row&7)
__device__ __half g_wcc[65 * 320 * 64];       // [slab][oc][64] sw(oc&7)
__device__ __half g_hc[19 * 16384 * 64];      // [kc][pos][64] sw(pos&7)
__device__ __half g_wec[19 * 512 * 64];       // [kc][oc][64] sw(oc&7)
__device__ float g_bconv[1200];

__constant__ int c_off[13] = {0,  0, 1,  -1, 0, 1,  -3, -2, -1, 0, 1, 2, 3};
__constant__ int c_base[4] = {0, 1, 3, 6};
__constant__ int c_nch[4]  = {5, 10, 15, 35};
__constant__ int c_sb[4]   = {0, 5, 15, 30};

// ------------------------- asm helpers -------------------------------------
__device__ __forceinline__ uint32_t smem_u32(const void* p) {
    uint32_t a;
    asm("{ .reg .u64 t; cvta.to.shared.u64 t, %1; cvt.u32.u64 %0, t; }"
        : "=r"(a) : "l"(p));
    return a;
}
#define BULK_G2S(dst, src, bytes, mbar)                                        \
    asm volatile(                                                              \
        "cp.async.bulk.shared::cluster.global.mbarrier::complete_tx::bytes "   \
        "[%0], [%1], %2, [%3];"                                                \
        :: "r"(dst), "l"(src), "r"(bytes), "r"(mbar) : "memory")
#define MBAR_INIT(a, c) \
    asm volatile("mbarrier.init.shared.b64 [%0], %1;" :: "r"(a), "r"(c) : "memory")
#define MBAR_EXPECT_TX(a, b) \
    asm volatile("mbarrier.arrive.expect_tx.shared.b64 _, [%0], %1;" \
                 :: "r"(a), "r"(b) : "memory")
#define MBAR_ARRIVE(a) \
    asm volatile("mbarrier.arrive.shared.b64 _, [%0];" :: "r"(a) : "memory")
#define FENCE_ASYNC() \
    asm volatile("fence.proxy.async.shared::cta;" ::: "memory")
__device__ __forceinline__ void mbar_wait(uint32_t a, uint32_t ph) {
    asm volatile(
        "{\n .reg .pred P;\nW%=:\n"
        " mbarrier.try_wait.parity.acquire.cta.shared::cta.b64 P, [%0], %1, 0x989680;\n"
        " @!P bra W%=;\n}"
        :: "r"(a), "r"(ph) : "memory");
}
#define LDSM4(R, A) \
    asm volatile("ldmatrix.sync.aligned.m8n8.x4.shared.b16 {%0,%1,%2,%3}, [%4];" \
                 : "=r"((R)[0]), "=r"((R)[1]), "=r"((R)[2]), "=r"((R)[3]) : "r"(A))
#define LDSM2(R, A) \
    asm volatile("ldmatrix.sync.aligned.m8n8.x2.shared.b16 {%0,%1}, [%2];" \
                 : "=r"((R)[0]), "=r"((R)[1]) : "r"(A))

__device__ __forceinline__ void mma16816(float* d, const uint32_t* a,
                                         const uint32_t* b) {
    asm volatile(
        "mma.sync.aligned.m16n8k16.row.col.f32.f16.f16.f32 "
        "{%0,%1,%2,%3}, {%4,%5,%6,%7}, {%8,%9}, {%0,%1,%2,%3};"
        : "+f"(d[0]), "+f"(d[1]), "+f"(d[2]), "+f"(d[3])
        : "r"(a[0]), "r"(a[1]), "r"(a[2]), "r"(a[3]), "r"(b[0]), "r"(b[1]));
}

// ------------------------- prep kernels (div/mod-free) ----------------------
// g_xc: grid (66, 5, 32), 256 thr; each thread writes one half2.
__global__ void prep_x(const float* __restrict__ x) {
    const int kc = blockIdx.y, b = blockIdx.z;
    const int r = blockIdx.x * 8 + (threadIdx.x >> 5);
    const int j = (threadIdx.x & 31) * 2;
    int rr = r - 8; rr = rr < 0 ? 0 : (rr > 511 ? 511 : rr);
    const int c = kc * 64 + j;
    const float* xr = x + ((size_t)(b * 512 + rr)) * 300;
    float v0 = (c < 300) ? xr[c] : 0.f;
    float v1 = (c + 1 < 300) ? xr[c + 1] : 0.f;
    __half2 hv; hv.x = __float2half_rn(v0); hv.y = __float2half_rn(v1);
    int pir = (((j >> 3) ^ (r & 7)) << 3) | (j & 7);
    *(__half2*)(g_xc + ((size_t)((b * 5 + kc) * 528 + r)) * 64 + pir) = hv;
}

// g_wcc: grid (40, 65), 256 thr; half2 per thread.
__global__ void prep_wc(const float* __restrict__ w1, const float* __restrict__ w2,
                        const float* __restrict__ w3, const float* __restrict__ w7) {
    const int s = blockIdx.y;
    const int oc = blockIdx.x * 8 + (threadIdx.x >> 5);
    const int j = (threadIdx.x & 31) * 2;
    int conv = (s < 5) ? 0 : (s < 15) ? 1 : (s < 30) ? 2 : 3;
    int sb = (conv == 0) ? 0 : (conv == 1) ? 5 : (conv == 2) ? 15 : 30;
    int rel = s - sb;
    int tap = rel / 5, kc = rel - (rel / 5) * 5;
    int ic = kc * 64 + j;
    float v0 = 0.f, v1 = 0.f;
    if (oc < 300) {
        const float* w; int K;
        if (conv == 0)      { w = w1; K = 1; }
        else if (conv == 1) { w = w2; K = 2; }
        else if (conv == 2) { w = w3; K = 3; }
        else                { w = w7; K = 7; }
        if (ic < 300)     v0 = w[(oc * 300 + ic) * K + tap];
        if (ic + 1 < 300) v1 = w[(oc * 300 + ic + 1) * K + tap];
    }
    __half2 hv; hv.x = __float2half_rn(v0); hv.y = __float2half_rn(v1);
    int pir = (((j >> 3) ^ (oc & 7)) << 3) | (j & 7);
    *(__half2*)(g_wcc + ((size_t)(s * 320 + oc)) * 64 + pir) = hv;
}

// g_wec + biases: grid (64, 19), 256 thr; half2 per thread.
__global__ void prep_we(const float* __restrict__ slp_w,
                        const float* __restrict__ b1, const float* __restrict__ b2,
                        const float* __restrict__ b3, const float* __restrict__ b7) {
    const int kc = blockIdx.y;
    const int oc = blockIdx.x * 8 + (threadIdx.x >> 5);
    const int j = (threadIdx.x & 31) * 2;
    const int ic = kc * 64 + j;
    const float* wr = slp_w + (size_t)oc * 1500;
    auto rd = [&](int i) -> float {
        if (i < 600)  return wr[i];
        if (i < 900)  return wr[i] + wr[i + 300];
        if (i < 1200) return wr[i + 300];
        return 0.f;
    };
    __half2 hv;
    hv.x = __float2half_rn(rd(ic));
    hv.y = __float2half_rn(rd(ic + 1));
    int pir = (((j >> 3) ^ (oc & 7)) << 3) | (j & 7);
    *(__half2*)(g_wec + ((size_t)(kc * 512 + oc)) * 64 + pir) = hv;
    if (kc == 0 && blockIdx.x < 5) {
        int idx = blockIdx.x * 256 + threadIdx.x;
        if (idx < 1200) {
            int conv = idx / 300, occ = idx - (idx / 300) * 300;
            const float* b = (conv == 0) ? b1 : (conv == 1) ? b2
                              : (conv == 2) ? b3 : b7;
            g_bconv[idx] = b[occ];
        }
    }
}

// ------------------------- conv GEMM kernel (BM=128, BN=160) ---------------
__global__ __launch_bounds__(512, 1)
void conv_mma_kernel() {
    extern __shared__ char sm[];
    const uint32_t smb = smem_u32(sm);
    const uint32_t mbF = smb + C_NBUF * CH_BUF;          // full barriers
    const uint32_t mbE = mbF + C_NBUF * 8;               // empty barriers
    const int tid = threadIdx.x, lane = tid & 31, wid = tid >> 5;
    const int wm = wid & 3, wn = wid >> 2;               // 4 x 4 warps
    const int quad = lane >> 2, kp2 = (lane & 3) * 2;

    const int conv = 3 - (int)(blockIdx.x >> 1);         // long convs first
    const int oc0  = (blockIdx.x & 1) * 160;
    const int pos0 = blockIdx.y * 128;
    const int bat = pos0 >> 9, l0 = pos0 & 511;
    const int nc = c_nch[conv];
    const int sbase = c_sb[conv];
    const int tb = c_base[conv];
    const bool cut = (oc0 == 160) && (wn == 3);          // cols >=304 dead

    if (tid == 0) {
#pragma unroll
        for (int i = 0; i < C_NBUF; ++i) {
            MBAR_INIT(mbF + i * 8, 1);
            MBAR_INIT(mbE + i * 8, 16);
        }
        FENCE_ASYNC();
    }
    __syncthreads();

    float acc[2][5][4];
#pragma unroll
    for (int mt = 0; mt < 2; ++mt)
#pragma unroll
        for (int nt = 0; nt < 5; ++nt)
#pragma unroll
            for (int e = 0; e < 4; ++e) acc[mt][nt][e] = 0.f;

    auto issue = [&](int ch, int buf) {  // thread 0 only
        int tap = ch / 5, kc = ch - tap * 5;
        int dlt = c_off[tb + tap];
        const char* a = (const char*)g_xc +
            ((size_t)((bat * 5 + kc) * 528 + 8 + l0 + dlt)) * 128;
        const char* b = (const char*)g_wcc +
            ((size_t)((sbase + ch) * 320 + oc0)) * 128;
        uint32_t d = smb + buf * CH_BUF;
        uint32_t m = mbF + buf * 8;
        MBAR_EXPECT_TX(m, CH_BUF);
        BULK_G2S(d + CH_A, a, 16384, m);
        BULK_G2S(d + CH_B, b, 20480, m);
    };

    if (tid == 0) {
#pragma unroll
        for (int i = 0; i < C_NBUF; ++i)
            if (i < nc) issue(i, i);
    }

    const int hi16 = lane >> 4;
    const int sbB = (lane >> 3) & 1;
    const int rmB = lane & 7;
    const uint32_t aRow  = (uint32_t)(wm * 32 + (lane & 15)) * 128;
    const uint32_t bRow  = (uint32_t)(wn * 40 + (lane & 7) +
                                      ((lane >> 4) & 1) * 8) * 128;
    const uint32_t bRow2 = (uint32_t)(wn * 40 + 32 + (lane & 7)) * 128;

    int buf = 0, ph = 0;
    for (int ch = 0; ch < nc; ++ch) {
        mbar_wait(mbF + buf * 8, ph);
        int tap = ch / 5;
        int adj = (8 + c_off[tb + tap]) & 7;             // A swizzle phase
        int rmA = ((lane & 15) + adj) & 7;
        const uint32_t Ab = smb + buf * CH_BUF + CH_A;
        const uint32_t Bb = smb + buf * CH_BUF + CH_B;
#pragma unroll
        for (int kk = 0; kk < 4; ++kk) {
            const uint32_t sA = (uint32_t)(((kk * 2 + hi16) ^ rmA) << 4);
            const uint32_t sB = (uint32_t)(((kk * 2 + sbB) ^ rmB) << 4);
            uint32_t ah[2][4];
            LDSM4(ah[0], Ab + aRow + sA);
            LDSM4(ah[1], Ab + aRow + 2048 + sA);
            uint32_t bh4[4];
            LDSM4(bh4, Bb + bRow + sB);
#pragma unroll
            for (int mt = 0; mt < 2; ++mt) {
                mma16816(acc[mt][0], ah[mt], bh4);
                mma16816(acc[mt][1], ah[mt], bh4 + 2);
            }
            LDSM4(bh4, Bb + bRow + 2048 + sB);
#pragma unroll
            for (int mt = 0; mt < 2; ++mt) {
                mma16816(acc[mt][2], ah[mt], bh4);
                mma16816(acc[mt][3], ah[mt], bh4 + 2);
            }
            if (!cut) {
                uint32_t bh2[2];
                LDSM2(bh2, Bb + bRow2 + sB);
#pragma unroll
                for (int mt = 0; mt < 2; ++mt)
                    mma16816(acc[mt][4], ah[mt], bh2);
            }
        }
        __syncwarp();
        if (lane == 0) MBAR_ARRIVE(mbE + buf * 8);
        if (tid == 0 && ch + C_NBUF < nc) {
            mbar_wait(mbE + buf * 8, ph);                // all 16 warps done
            issue(ch + C_NBUF, buf);
        }
        if (++buf == C_NBUF) { buf = 0; ph ^= 1; }
    }

    // epilogue: tanh(acc + bias) -> chunked+swizzled fp16 h
#pragma unroll
    for (int mt = 0; mt < 2; ++mt) {
        int r0 = pos0 + wm * 32 + mt * 16 + quad;
#pragma unroll
        for (int nt = 0; nt < 5; ++nt) {
            int col = oc0 + wn * 40 + nt * 8 + kp2;
            if (col >= 300) continue;
            int gc = conv * 300 + col;
            int kc = gc >> 6, j = gc & 63;
            float bi0 = g_bconv[gc], bi1 = g_bconv[gc + 1];
#pragma unroll
            for (int half = 0; half < 2; ++half) {
                int r = r0 + half * 8;
                __half2 hv;
                hv.x = __float2half_rn(tanhf(acc[mt][nt][half * 2 + 0] + bi0));
                hv.y = __float2half_rn(tanhf(acc[mt][nt][half * 2 + 1] + bi1));
                int pir = (((j >> 3) ^ (r & 7)) << 3) | (j & 7);
                *(__half2*)(g_hc + ((size_t)kc * 16384 + r) * 64 + pir) = hv;
            }
        }
    }
}

// ------------------------- SLP GEMM kernel (256 thr, 2 CTAs/SM) ------------
__global__ __launch_bounds__(256, 2)
void slp_mma_kernel(const float* __restrict__ slp_b, float* __restrict__ out) {
    extern __shared__ char sm[];
    const uint32_t smb = smem_u32(sm);
    const uint32_t mbF = smb + S_NBUF * SL_BUF;
    const uint32_t mbE = mbF + S_NBUF * 8;
    const int tid = threadIdx.x, lane = tid & 31, wid = tid >> 5;
    const int wm = wid >> 2, wn = wid & 3;               // 2 x 4 warps
    const int quad = lane >> 2, kp2 = (lane & 3) * 2;
    const int oc0  = blockIdx.x * 128;
    const int pos0 = blockIdx.y * 128;
    const int nc = 19;
    const int rmA = lane & 7;

    if (tid == 0) {
#pragma unroll
        for (int i = 0; i < S_NBUF; ++i) {
            MBAR_INIT(mbF + i * 8, 1);
            MBAR_INIT(mbE + i * 8, 8);
        }
        FENCE_ASYNC();
    }
    __syncthreads();

    float acc[4][4][4];
#pragma unroll
    for (int mt = 0; mt < 4; ++mt)
#pragma unroll
        for (int nt = 0; nt < 4; ++nt)
#pragma unroll
            for (int e = 0; e < 4; ++e) acc[mt][nt][e] = 0.f;

    auto issue = [&](int ch, int buf) {
        const char* a = (const char*)g_hc + ((size_t)ch * 16384 + pos0) * 128;
        const char* b = (const char*)g_wec + ((size_t)ch * 512 + oc0) * 128;
        uint32_t d = smb + buf * SL_BUF;
        uint32_t m = mbF + buf * 8;
        MBAR_EXPECT_TX(m, SL_BUF);
        BULK_G2S(d + SL_A, a, 16384, m);
        BULK_G2S(d + SL_B, b, 16384, m);
    };

    if (tid == 0) { issue(0, 0); issue(1, 1); issue(2, 2); }

    const int hi16 = lane >> 4;
    const int sbB = (lane >> 3) & 1;
    const int rmB = lane & 7;
    const uint32_t aRow  = (uint32_t)(wm * 64 + (lane & 15)) * 128;
    const uint32_t bRow  = (uint32_t)(wn * 32 + (lane & 7) +
                                      ((lane >> 4) & 1) * 8) * 128;

    int buf = 0, ph = 0;
    for (int ch = 0; ch < nc; ++ch) {
        mbar_wait(mbF + buf * 8, (ch / S_NBUF) & 1);
        const uint32_t Ab = smb + buf * SL_BUF + SL_A;
        const uint32_t Bb = smb + buf * SL_BUF + SL_B;
#pragma unroll
        for (int kk = 0; kk < 4; ++kk) {
            const uint32_t sA = (uint32_t)(((kk * 2 + hi16) ^ rmA) << 4);
            const uint32_t sB = (uint32_t)(((kk * 2 + sbB) ^ rmB) << 4);
            uint32_t ah[4][4];
#pragma unroll
            for (int mt = 0; mt < 4; ++mt)
                LDSM4(ah[mt], Ab + aRow + mt * 2048 + sA);
#pragma unroll
            for (int p = 0; p < 2; ++p) {
                uint32_t bh[4];
                LDSM4(bh, Bb + bRow + p * 2048 + sB);
#pragma unroll
                for (int q = 0; q < 2; ++q)
#pragma unroll
                    for (int mt = 0; mt < 4; ++mt)
                        mma16816(acc[mt][p * 2 + q], ah[mt], bh + q * 2);
            }
        }
        __syncwarp();
        if (lane == 0) MBAR_ARRIVE(mbE + buf * 8);
        if (tid == 0 && ch + S_NBUF < nc) {
            mbar_wait(mbE + buf * 8, ph);
            issue(ch + S_NBUF, buf);
        }
        if (++buf == S_NBUF) { buf = 0; ph ^= 1; }
    }

#pragma unroll
    for (int mt = 0; mt < 4; ++mt) {
        int r0 = pos0 + wm * 64 + mt * 16 + quad;
#pragma unroll
        for (int nt = 0; nt < 4; ++nt) {
            int col = oc0 + wn * 32 + nt * 8 + kp2;
            float bi0 = slp_b[col], bi1 = slp_b[col + 1];
#pragma unroll
            for (int half = 0; half < 2; ++half) {
                int r = r0 + half * 8;
                float2 v;
                v.x = tanhf(acc[mt][nt][half * 2 + 0] + bi0);
                v.y = tanhf(acc[mt][nt][half * 2 + 1] + bi1);
                *(float2*)(out + (size_t)r * 512 + col) = v;
            }
        }
    }
}

// ------------------------- launch ------------------------------------------
extern "C" void kernel_launch(void* const* d_in, const int* in_sizes, int n_in,
                              void* d_out, int out_size) {
    const float* x     = (const float*)d_in[0];
    const float* w1    = (const float*)d_in[1];
    const float* b1    = (const float*)d_in[2];
    const float* w2    = (const float*)d_in[3];
    const float* b2    = (const float*)d_in[4];
    const float* w3    = (const float*)d_in[5];
    const float* b3    = (const float*)d_in[6];
    const float* w7    = (const float*)d_in[7];
    const float* b7    = (const float*)d_in[8];
    const float* slp_w = (const float*)d_in[9];
    const float* slp_b = (const float*)d_in[10];
    float* out = (float*)d_out;
    (void)b2; (void)b3;

    cudaFuncSetAttribute(conv_mma_kernel, cudaFuncAttributeMaxDynamicSharedMemorySize, CONV_SMEM);
    cudaFuncSetAttribute(slp_mma_kernel,  cudaFuncAttributeMaxDynamicSharedMemorySize, SLP_SMEM);

    prep_x<<<dim3(66, 5, 32), 256>>>(x);
    prep_wc<<<dim3(40, 65), 256>>>(w1, w2, w3, w7);
    prep_we<<<dim3(64, 19), 256>>>(slp_w, b1, b2, b3, b7);

    conv_mma_kernel<<<dim3(8, 128), 512, CONV_SMEM>>>();
    slp_mma_kernel<<<dim3(4, 128), 256, SLP_SMEM>>>(slp_b, out);
}

// round 14
// speedup vs baseline: 1.0802x; 1.0076x over previous
#include <cuda_runtime.h>
#include <cuda_fp16.h>
#include <math.h>
#include <stdint.h>

// ===========================================================================
// TxtNet, single-term fp16 HMMA.16816 (fp32 accum) fed by cp.async.bulk.
// R14 = R13 + zero-K-step skip: the pad region ic 304..319 of each tap (and
// ic 1200..1215 in slp) is identically zero, so its k16 step is skipped
// (conv MMAs -5%, slp -1.3%, numerically exact). Conv pipeline 6 buffers.
// Conv: 4 GEMMs, K=ntap*320. SLP: 16384 x 1216 x 512 (x5==x3 fold).
// ===========================================================================

#define P_TOT 16384

// conv smem: A 16K + B 20K per buffer, 6 buffers
#define CH_A 0
#define CH_B 16384
#define CH_BUF 36864
#define C_NBUF 6
#define CONV_SMEM (C_NBUF * CH_BUF + 128)     // 221312
// slp smem: A 16K + B 16K per buffer, 3 buffers, 2 CTAs/SM
#define SL_A 0
#define SL_B 16384
#define SL_BUF 32768
#define S_NBUF 3
#define SLP_SMEM (S_NBUF * SL_BUF + 128)

// ------------------------- device scratch (zero-init) ----------------------
__device__ __half g_xc[32 * 5 * 528 * 64];    // [b][kc][row 528 pad][64] sw(row&7)
__device__ __half g_wcc[65 * 320 * 64];       // [slab][oc][64] sw(oc&7)
__device__ __half g_hc[19 * 16384 * 64];      // [kc][pos][64] sw(pos&7)
__device__ __half g_wec[19 * 512 * 64];       // [kc][oc][64] sw(oc&7)
__device__ float g_bconv[1200];

__constant__ int c_off[13] = {0,  0, 1,  -1, 0, 1,  -3, -2, -1, 0, 1, 2, 3};
__constant__ int c_base[4] = {0, 1, 3, 6};
__constant__ int c_nch[4]  = {5, 10, 15, 35};
__constant__ int c_sb[4]   = {0, 5, 15, 30};

// ------------------------- asm helpers -------------------------------------
__device__ __forceinline__ uint32_t smem_u32(const void* p) {
    uint32_t a;
    asm("{ .reg .u64 t; cvta.to.shared.u64 t, %1; cvt.u32.u64 %0, t; }"
        : "=r"(a) : "l"(p));
    return a;
}
#define BULK_G2S(dst, src, bytes, mbar)                                        \
    asm volatile(                                                              \
        "cp.async.bulk.shared::cluster.global.mbarrier::complete_tx::bytes "   \
        "[%0], [%1], %2, [%3];"                                                \
        :: "r"(dst), "l"(src), "r"(bytes), "r"(mbar) : "memory")
#define MBAR_INIT(a, c) \
    asm volatile("mbarrier.init.shared.b64 [%0], %1;" :: "r"(a), "r"(c) : "memory")
#define MBAR_EXPECT_TX(a, b) \
    asm volatile("mbarrier.arrive.expect_tx.shared.b64 _, [%0], %1;" \
                 :: "r"(a), "r"(b) : "memory")
#define MBAR_ARRIVE(a) \
    asm volatile("mbarrier.arrive.shared.b64 _, [%0];" :: "r"(a) : "memory")
#define FENCE_ASYNC() \
    asm volatile("fence.proxy.async.shared::cta;" ::: "memory")
__device__ __forceinline__ void mbar_wait(uint32_t a, uint32_t ph) {
    asm volatile(
        "{\n .reg .pred P;\nW%=:\n"
        " mbarrier.try_wait.parity.acquire.cta.shared::cta.b64 P, [%0], %1, 0x989680;\n"
        " @!P bra W%=;\n}"
        :: "r"(a), "r"(ph) : "memory");
}
#define LDSM4(R, A) \
    asm volatile("ldmatrix.sync.aligned.m8n8.x4.shared.b16 {%0,%1,%2,%3}, [%4];" \
                 : "=r"((R)[0]), "=r"((R)[1]), "=r"((R)[2]), "=r"((R)[3]) : "r"(A))
#define LDSM2(R, A) \
    asm volatile("ldmatrix.sync.aligned.m8n8.x2.shared.b16 {%0,%1}, [%2];" \
                 : "=r"((R)[0]), "=r"((R)[1]) : "r"(A))

__device__ __forceinline__ void mma16816(float* d, const uint32_t* a,
                                         const uint32_t* b) {
    asm volatile(
        "mma.sync.aligned.m16n8k16.row.col.f32.f16.f16.f32 "
        "{%0,%1,%2,%3}, {%4,%5,%6,%7}, {%8,%9}, {%0,%1,%2,%3};"
        : "+f"(d[0]), "+f"(d[1]), "+f"(d[2]), "+f"(d[3])
        : "r"(a[0]), "r"(a[1]), "r"(a[2]), "r"(a[3]), "r"(b[0]), "r"(b[1]));
}

// ------------------------- prep kernels (div/mod-free) ----------------------
__global__ void prep_x(const float* __restrict__ x) {
    const int kc = blockIdx.y, b = blockIdx.z;
    const int r = blockIdx.x * 8 + (threadIdx.x >> 5);
    const int j = (threadIdx.x & 31) * 2;
    int rr = r - 8; rr = rr < 0 ? 0 : (rr > 511 ? 511 : rr);
    const int c = kc * 64 + j;
    const float* xr = x + ((size_t)(b * 512 + rr)) * 300;
    float v0 = (c < 300) ? xr[c] : 0.f;
    float v1 = (c + 1 < 300) ? xr[c + 1] : 0.f;
    __half2 hv; hv.x = __float2half_rn(v0); hv.y = __float2half_rn(v1);
    int pir = (((j >> 3) ^ (r & 7)) << 3) | (j & 7);
    *(__half2*)(g_xc + ((size_t)((b * 5 + kc) * 528 + r)) * 64 + pir) = hv;
}

__global__ void prep_wc(const float* __restrict__ w1, const float* __restrict__ w2,
                        const float* __restrict__ w3, const float* __restrict__ w7) {
    const int s = blockIdx.y;
    const int oc = blockIdx.x * 8 + (threadIdx.x >> 5);
    const int j = (threadIdx.x & 31) * 2;
    int conv = (s < 5) ? 0 : (s < 15) ? 1 : (s < 30) ? 2 : 3;
    int sb = (conv == 0) ? 0 : (conv == 1) ? 5 : (conv == 2) ? 15 : 30;
    int rel = s - sb;
    int tap = rel / 5, kc = rel - (rel / 5) * 5;
    int ic = kc * 64 + j;
    float v0 = 0.f, v1 = 0.f;
    if (oc < 300) {
        const float* w; int K;
        if (conv == 0)      { w = w1; K = 1; }
        else if (conv == 1) { w = w2; K = 2; }
        else if (conv == 2) { w = w3; K = 3; }
        else                { w = w7; K = 7; }
        if (ic < 300)     v0 = w[(oc * 300 + ic) * K + tap];
        if (ic + 1 < 300) v1 = w[(oc * 300 + ic + 1) * K + tap];
    }
    __half2 hv; hv.x = __float2half_rn(v0); hv.y = __float2half_rn(v1);
    int pir = (((j >> 3) ^ (oc & 7)) << 3) | (j & 7);
    *(__half2*)(g_wcc + ((size_t)(s * 320 + oc)) * 64 + pir) = hv;
}

__global__ void prep_we(const float* __restrict__ slp_w,
                        const float* __restrict__ b1, const float* __restrict__ b2,
                        const float* __restrict__ b3, const float* __restrict__ b7) {
    const int kc = blockIdx.y;
    const int oc = blockIdx.x * 8 + (threadIdx.x >> 5);
    const int j = (threadIdx.x & 31) * 2;
    const int ic = kc * 64 + j;
    const float* wr = slp_w + (size_t)oc * 1500;
    auto rd = [&](int i) -> float {
        if (i < 600)  return wr[i];
        if (i < 900)  return wr[i] + wr[i + 300];
        if (i < 1200) return wr[i + 300];
        return 0.f;
    };
    __half2 hv;
    hv.x = __float2half_rn(rd(ic));
    hv.y = __float2half_rn(rd(ic + 1));
    int pir = (((j >> 3) ^ (oc & 7)) << 3) | (j & 7);
    *(__half2*)(g_wec + ((size_t)(kc * 512 + oc)) * 64 + pir) = hv;
    if (kc == 0 && blockIdx.x < 5) {
        int idx = blockIdx.x * 256 + threadIdx.x;
        if (idx < 1200) {
            int conv = idx / 300, occ = idx - (idx / 300) * 300;
            const float* b = (conv == 0) ? b1 : (conv == 1) ? b2
                              : (conv == 2) ? b3 : b7;
            g_bconv[idx] = b[occ];
        }
    }
}

// ------------------------- conv GEMM kernel (BM=128, BN=160) ---------------
__global__ __launch_bounds__(512, 1)
void conv_mma_kernel() {
    extern __shared__ char sm[];
    const uint32_t smb = smem_u32(sm);
    const uint32_t mbF = smb + C_NBUF * CH_BUF;          // full barriers
    const uint32_t mbE = mbF + C_NBUF * 8;               // empty barriers
    const int tid = threadIdx.x, lane = tid & 31, wid = tid >> 5;
    const int wm = wid & 3, wn = wid >> 2;               // 4 x 4 warps
    const int quad = lane >> 2, kp2 = (lane & 3) * 2;

    const int conv = 3 - (int)(blockIdx.x >> 1);         // long convs first
    const int oc0  = (blockIdx.x & 1) * 160;
    const int pos0 = blockIdx.y * 128;
    const int bat = pos0 >> 9, l0 = pos0 & 511;
    const int nc = c_nch[conv];
    const int sbase = c_sb[conv];
    const int tb = c_base[conv];
    const bool cut = (oc0 == 160) && (wn == 3);          // cols >=304 dead

    if (tid == 0) {
#pragma unroll
        for (int i = 0; i < C_NBUF; ++i) {
            MBAR_INIT(mbF + i * 8, 1);
            MBAR_INIT(mbE + i * 8, 16);
        }
        FENCE_ASYNC();
    }
    __syncthreads();

    float acc[2][5][4];
#pragma unroll
    for (int mt = 0; mt < 2; ++mt)
#pragma unroll
        for (int nt = 0; nt < 5; ++nt)
#pragma unroll
            for (int e = 0; e < 4; ++e) acc[mt][nt][e] = 0.f;

    auto issue = [&](int ch, int buf) {  // thread 0 only
        int tap = ch / 5, kc = ch - tap * 5;
        int dlt = c_off[tb + tap];
        const char* a = (const char*)g_xc +
            ((size_t)((bat * 5 + kc) * 528 + 8 + l0 + dlt)) * 128;
        const char* b = (const char*)g_wcc +
            ((size_t)((sbase + ch) * 320 + oc0)) * 128;
        uint32_t d = smb + buf * CH_BUF;
        uint32_t m = mbF + buf * 8;
        MBAR_EXPECT_TX(m, CH_BUF);
        BULK_G2S(d + CH_A, a, 16384, m);
        BULK_G2S(d + CH_B, b, 20480, m);
    };

    if (tid == 0) {
#pragma unroll
        for (int i = 0; i < C_NBUF; ++i)
            if (i < nc) issue(i, i);
    }

    const int hi16 = lane >> 4;
    const int sbB = (lane >> 3) & 1;
    const int rmB = lane & 7;
    const uint32_t aRow  = (uint32_t)(wm * 32 + (lane & 15)) * 128;
    const uint32_t bRow  = (uint32_t)(wn * 40 + (lane & 7) +
                                      ((lane >> 4) & 1) * 8) * 128;
    const uint32_t bRow2 = (uint32_t)(wn * 40 + 32 + (lane & 7)) * 128;

    int buf = 0, ph = 0;
    for (int ch = 0; ch < nc; ++ch) {
        mbar_wait(mbF + buf * 8, ph);
        int tap = ch / 5;
        int kcl = ch - tap * 5;
        int adj = (8 + c_off[tb + tap]) & 7;             // A swizzle phase
        int rmA = ((lane & 15) + adj) & 7;
        const uint32_t Ab = smb + buf * CH_BUF + CH_A;
        const uint32_t Bb = smb + buf * CH_BUF + CH_B;

        auto kstep = [&](int kk) {
            const uint32_t sA = (uint32_t)(((kk * 2 + hi16) ^ rmA) << 4);
            const uint32_t sB = (uint32_t)(((kk * 2 + sbB) ^ rmB) << 4);
            uint32_t ah[2][4];
            LDSM4(ah[0], Ab + aRow + sA);
            LDSM4(ah[1], Ab + aRow + 2048 + sA);
            uint32_t bh4[4];
            LDSM4(bh4, Bb + bRow + sB);
#pragma unroll
            for (int mt = 0; mt < 2; ++mt) {
                mma16816(acc[mt][0], ah[mt], bh4);
                mma16816(acc[mt][1], ah[mt], bh4 + 2);
            }
            LDSM4(bh4, Bb + bRow + 2048 + sB);
#pragma unroll
            for (int mt = 0; mt < 2; ++mt) {
                mma16816(acc[mt][2], ah[mt], bh4);
                mma16816(acc[mt][3], ah[mt], bh4 + 2);
            }
            if (!cut) {
                uint32_t bh2[2];
                LDSM2(bh2, Bb + bRow2 + sB);
#pragma unroll
                for (int mt = 0; mt < 2; ++mt)
                    mma16816(acc[mt][4], ah[mt], bh2);
            }
        };

        kstep(0);
        kstep(1);
        kstep(2);
        if (kcl != 4) kstep(3);          // ic 304..319 is zero pad: skip
        __syncwarp();
        if (lane == 0) MBAR_ARRIVE(mbE + buf * 8);
        if (tid == 0 && ch + C_NBUF < nc) {
            mbar_wait(mbE + buf * 8, ph);                // all 16 warps done
            issue(ch + C_NBUF, buf);
        }
        if (++buf == C_NBUF) { buf = 0; ph ^= 1; }
    }

    // epilogue: tanh(acc + bias) -> chunked+swizzled fp16 h
#pragma unroll
    for (int mt = 0; mt < 2; ++mt) {
        int r0 = pos0 + wm * 32 + mt * 16 + quad;
#pragma unroll
        for (int nt = 0; nt < 5; ++nt) {
            int col = oc0 + wn * 40 + nt * 8 + kp2;
            if (col >= 300) continue;
            int gc = conv * 300 + col;
            int kc = gc >> 6, j = gc & 63;
            float bi0 = g_bconv[gc], bi1 = g_bconv[gc + 1];
#pragma unroll
            for (int half = 0; half < 2; ++half) {
                int r = r0 + half * 8;
                __half2 hv;
                hv.x = __float2half_rn(tanhf(acc[mt][nt][half * 2 + 0] + bi0));
                hv.y = __float2half_rn(tanhf(acc[mt][nt][half * 2 + 1] + bi1));
                int pir = (((j >> 3) ^ (r & 7)) << 3) | (j & 7);
                *(__half2*)(g_hc + ((size_t)kc * 16384 + r) * 64 + pir) = hv;
            }
        }
    }
}

// ------------------------- SLP GEMM kernel (256 thr, 2 CTAs/SM) ------------
__global__ __launch_bounds__(256, 2)
void slp_mma_kernel(const float* __restrict__ slp_b, float* __restrict__ out) {
    extern __shared__ char sm[];
    const uint32_t smb = smem_u32(sm);
    const uint32_t mbF = smb + S_NBUF * SL_BUF;
    const uint32_t mbE = mbF + S_NBUF * 8;
    const int tid = threadIdx.x, lane = tid & 31, wid = tid >> 5;
    const int wm = wid >> 2, wn = wid & 3;               // 2 x 4 warps
    const int quad = lane >> 2, kp2 = (lane & 3) * 2;
    const int oc0  = blockIdx.x * 128;
    const int pos0 = blockIdx.y * 128;
    const int nc = 19;
    const int rmA = lane & 7;

    if (tid == 0) {
#pragma unroll
        for (int i = 0; i < S_NBUF; ++i) {
            MBAR_INIT(mbF + i * 8, 1);
            MBAR_INIT(mbE + i * 8, 8);
        }
        FENCE_ASYNC();
    }
    __syncthreads();

    float acc[4][4][4];
#pragma unroll
    for (int mt = 0; mt < 4; ++mt)
#pragma unroll
        for (int nt = 0; nt < 4; ++nt)
#pragma unroll
            for (int e = 0; e < 4; ++e) acc[mt][nt][e] = 0.f;

    auto issue = [&](int ch, int buf) {
        const char* a = (const char*)g_hc + ((size_t)ch * 16384 + pos0) * 128;
        const char* b = (const char*)g_wec + ((size_t)ch * 512 + oc0) * 128;
        uint32_t d = smb + buf * SL_BUF;
        uint32_t m = mbF + buf * 8;
        MBAR_EXPECT_TX(m, SL_BUF);
        BULK_G2S(d + SL_A, a, 16384, m);
        BULK_G2S(d + SL_B, b, 16384, m);
    };

    if (tid == 0) { issue(0, 0); issue(1, 1); issue(2, 2); }

    const int hi16 = lane >> 4;
    const int sbB = (lane >> 3) & 1;
    const int rmB = lane & 7;
    const uint32_t aRow  = (uint32_t)(wm * 64 + (lane & 15)) * 128;
    const uint32_t bRow  = (uint32_t)(wn * 32 + (lane & 7) +
                                      ((lane >> 4) & 1) * 8) * 128;

    int buf = 0, ph = 0;
    for (int ch = 0; ch < nc; ++ch) {
        mbar_wait(mbF + buf * 8, (ch / S_NBUF) & 1);
        const uint32_t Ab = smb + buf * SL_BUF + SL_A;
        const uint32_t Bb = smb + buf * SL_BUF + SL_B;

        auto kstep = [&](int kk) {
            const uint32_t sA = (uint32_t)(((kk * 2 + hi16) ^ rmA) << 4);
            const uint32_t sB = (uint32_t)(((kk * 2 + sbB) ^ rmB) << 4);
            uint32_t ah[4][4];
#pragma unroll
            for (int mt = 0; mt < 4; ++mt)
                LDSM4(ah[mt], Ab + aRow + mt * 2048 + sA);
#pragma unroll
            for (int p = 0; p < 2; ++p) {
                uint32_t bh[4];
                LDSM4(bh, Bb + bRow + p * 2048 + sB);
#pragma unroll
                for (int q = 0; q < 2; ++q)
#pragma unroll
                    for (int mt = 0; mt < 4; ++mt)
                        mma16816(acc[mt][p * 2 + q], ah[mt], bh + q * 2);
            }
        };

        kstep(0);
        kstep(1);
        kstep(2);
        if (ch != 18) kstep(3);          // ic 1200..1215 is zero pad: skip
        __syncwarp();
        if (lane == 0) MBAR_ARRIVE(mbE + buf * 8);
        if (tid == 0 && ch + S_NBUF < nc) {
            mbar_wait(mbE + buf * 8, ph);
            issue(ch + S_NBUF, buf);
        }
        if (++buf == S_NBUF) { buf = 0; ph ^= 1; }
    }

#pragma unroll
    for (int mt = 0; mt < 4; ++mt) {
        int r0 = pos0 + wm * 64 + mt * 16 + quad;
#pragma unroll
        for (int nt = 0; nt < 4; ++nt) {
            int col = oc0 + wn * 32 + nt * 8 + kp2;
            float bi0 = slp_b[col], bi1 = slp_b[col + 1];
#pragma unroll
            for (int half = 0; half < 2; ++half) {
                int r = r0 + half * 8;
                float2 v;
                v.x = tanhf(acc[mt][nt][half * 2 + 0] + bi0);
                v.y = tanhf(acc[mt][nt][half * 2 + 1] + bi1);
                *(float2*)(out + (size_t)r * 512 + col) = v;
            }
        }
    }
}

// ------------------------- launch ------------------------------------------
extern "C" void kernel_launch(void* const* d_in, const int* in_sizes, int n_in,
                              void* d_out, int out_size) {
    const float* x     = (const float*)d_in[0];
    const float* w1    = (const float*)d_in[1];
    const float* b1    = (const float*)d_in[2];
    const float* w2    = (const float*)d_in[3];
    const float* b2    = (const float*)d_in[4];
    const float* w3    = (const float*)d_in[5];
    const float* b3    = (const float*)d_in[6];
    const float* w7    = (const float*)d_in[7];
    const float* b7    = (const float*)d_in[8];
    const float* slp_w = (const float*)d_in[9];
    const float* slp_b = (const float*)d_in[10];
    float* out = (float*)d_out;
    (void)b2; (void)b3;

    cudaFuncSetAttribute(conv_mma_kernel, cudaFuncAttributeMaxDynamicSharedMemorySize, CONV_SMEM);
    cudaFuncSetAttribute(slp_mma_kernel,  cudaFuncAttributeMaxDynamicSharedMemorySize, SLP_SMEM);

    prep_x<<<dim3(66, 5, 32), 256>>>(x);
    prep_wc<<<dim3(40, 65), 256>>>(w1, w2, w3, w7);
    prep_we<<<dim3(64, 19), 256>>>(slp_w, b1, b2, b3, b7);

    conv_mma_kernel<<<dim3(8, 128), 512, CONV_SMEM>>>();
    slp_mma_kernel<<<dim3(4, 128), 256, SLP_SMEM>>>(slp_b, out);
}

// round 15
// speedup vs baseline: 1.1022x; 1.0203x over previous
#include <cuda_runtime.h>
#include <cuda_fp16.h>
#include <math.h>
#include <stdint.h>

// ===========================================================================
// TxtNet, single-term fp16 HMMA.16816 (fp32 accum) fed by cp.async.bulk.
// R15 = R14 + conv MACRO-CHUNKS: per tap, 3 chunks [128K,128K,64K] instead of
// five 64K chunks. Each buffer = up to 2 kc-slabs (2 A + 2 B bulks, ONE
// mbarrier transaction), cutting per-chunk waits/arrives/loop overhead 40%
// while keeping bulk count, MMA count and numerics identical.
// Conv: 4 GEMMs, K=ntap*320 (zero-pad k-step skipped). SLP: 16384x1216x512.
// ===========================================================================

#define P_TOT 16384

// conv smem: per buffer 2x(A 16K) + 2x(B 20K) = 72K, 3 buffers
#define CH_A 0
#define CH_B 32768
#define CH_BUF 73728
#define C_NBUF 3
#define CONV_SMEM (C_NBUF * CH_BUF + 128)     // 221312
// slp smem: A 16K + B 16K per buffer, 3 buffers, 2 CTAs/SM
#define SL_A 0
#define SL_B 16384
#define SL_BUF 32768
#define S_NBUF 3
#define SLP_SMEM (S_NBUF * SL_BUF + 128)

// ------------------------- device scratch (zero-init) ----------------------
__device__ __half g_xc[32 * 5 * 528 * 64];    // [b][kc][row 528 pad][64] sw(row&7)
__device__ __half g_wcc[65 * 320 * 64];       // [slab][oc][64] sw(oc&7)
__device__ __half g_hc[19 * 16384 * 64];      // [kc][pos][64] sw(pos&7)
__device__ __half g_wec[19 * 512 * 64];       // [kc][oc][64] sw(oc&7)
__device__ float g_bconv[1200];

__constant__ int c_off[13] = {0,  0, 1,  -1, 0, 1,  -3, -2, -1, 0, 1, 2, 3};
__constant__ int c_base[4] = {0, 1, 3, 6};
__constant__ int c_nch[4]  = {3, 6, 9, 21};   // macro-chunks per conv (3/tap)
__constant__ int c_sb[4]   = {0, 5, 15, 30};

// ------------------------- asm helpers -------------------------------------
__device__ __forceinline__ uint32_t smem_u32(const void* p) {
    uint32_t a;
    asm("{ .reg .u64 t; cvta.to.shared.u64 t, %1; cvt.u32.u64 %0, t; }"
        : "=r"(a) : "l"(p));
    return a;
}
#define BULK_G2S(dst, src, bytes, mbar)                                        \
    asm volatile(                                                              \
        "cp.async.bulk.shared::cluster.global.mbarrier::complete_tx::bytes "   \
        "[%0], [%1], %2, [%3];"                                                \
        :: "r"(dst), "l"(src), "r"(bytes), "r"(mbar) : "memory")
#define MBAR_INIT(a, c) \
    asm volatile("mbarrier.init.shared.b64 [%0], %1;" :: "r"(a), "r"(c) : "memory")
#define MBAR_EXPECT_TX(a, b) \
    asm volatile("mbarrier.arrive.expect_tx.shared.b64 _, [%0], %1;" \
                 :: "r"(a), "r"(b) : "memory")
#define MBAR_ARRIVE(a) \
    asm volatile("mbarrier.arrive.shared.b64 _, [%0];" :: "r"(a) : "memory")
#define FENCE_ASYNC() \
    asm volatile("fence.proxy.async.shared::cta;" ::: "memory")
__device__ __forceinline__ void mbar_wait(uint32_t a, uint32_t ph) {
    asm volatile(
        "{\n .reg .pred P;\nW%=:\n"
        " mbarrier.try_wait.parity.acquire.cta.shared::cta.b64 P, [%0], %1, 0x989680;\n"
        " @!P bra W%=;\n}"
        :: "r"(a), "r"(ph) : "memory");
}
#define LDSM4(R, A) \
    asm volatile("ldmatrix.sync.aligned.m8n8.x4.shared.b16 {%0,%1,%2,%3}, [%4];" \
                 : "=r"((R)[0]), "=r"((R)[1]), "=r"((R)[2]), "=r"((R)[3]) : "r"(A))
#define LDSM2(R, A) \
    asm volatile("ldmatrix.sync.aligned.m8n8.x2.shared.b16 {%0,%1}, [%2];" \
                 : "=r"((R)[0]), "=r"((R)[1]) : "r"(A))

__device__ __forceinline__ void mma16816(float* d, const uint32_t* a,
                                         const uint32_t* b) {
    asm volatile(
        "mma.sync.aligned.m16n8k16.row.col.f32.f16.f16.f32 "
        "{%0,%1,%2,%3}, {%4,%5,%6,%7}, {%8,%9}, {%0,%1,%2,%3};"
        : "+f"(d[0]), "+f"(d[1]), "+f"(d[2]), "+f"(d[3])
        : "r"(a[0]), "r"(a[1]), "r"(a[2]), "r"(a[3]), "r"(b[0]), "r"(b[1]));
}

// ------------------------- prep kernels (div/mod-free) ----------------------
__global__ void prep_x(const float* __restrict__ x) {
    const int kc = blockIdx.y, b = blockIdx.z;
    const int r = blockIdx.x * 8 + (threadIdx.x >> 5);
    const int j = (threadIdx.x & 31) * 2;
    int rr = r - 8; rr = rr < 0 ? 0 : (rr > 511 ? 511 : rr);
    const int c = kc * 64 + j;
    const float* xr = x + ((size_t)(b * 512 + rr)) * 300;
    float v0 = (c < 300) ? xr[c] : 0.f;
    float v1 = (c + 1 < 300) ? xr[c + 1] : 0.f;
    __half2 hv; hv.x = __float2half_rn(v0); hv.y = __float2half_rn(v1);
    int pir = (((j >> 3) ^ (r & 7)) << 3) | (j & 7);
    *(__half2*)(g_xc + ((size_t)((b * 5 + kc) * 528 + r)) * 64 + pir) = hv;
}

__global__ void prep_wc(const float* __restrict__ w1, const float* __restrict__ w2,
                        const float* __restrict__ w3, const float* __restrict__ w7) {
    const int s = blockIdx.y;
    const int oc = blockIdx.x * 8 + (threadIdx.x >> 5);
    const int j = (threadIdx.x & 31) * 2;
    int conv = (s < 5) ? 0 : (s < 15) ? 1 : (s < 30) ? 2 : 3;
    int sb = (conv == 0) ? 0 : (conv == 1) ? 5 : (conv == 2) ? 15 : 30;
    int rel = s - sb;
    int tap = rel / 5, kc = rel - (rel / 5) * 5;
    int ic = kc * 64 + j;
    float v0 = 0.f, v1 = 0.f;
    if (oc < 300) {
        const float* w; int K;
        if (conv == 0)      { w = w1; K = 1; }
        else if (conv == 1) { w = w2; K = 2; }
        else if (conv == 2) { w = w3; K = 3; }
        else                { w = w7; K = 7; }
        if (ic < 300)     v0 = w[(oc * 300 + ic) * K + tap];
        if (ic + 1 < 300) v1 = w[(oc * 300 + ic + 1) * K + tap];
    }
    __half2 hv; hv.x = __float2half_rn(v0); hv.y = __float2half_rn(v1);
    int pir = (((j >> 3) ^ (oc & 7)) << 3) | (j & 7);
    *(__half2*)(g_wcc + ((size_t)(s * 320 + oc)) * 64 + pir) = hv;
}

__global__ void prep_we(const float* __restrict__ slp_w,
                        const float* __restrict__ b1, const float* __restrict__ b2,
                        const float* __restrict__ b3, const float* __restrict__ b7) {
    const int kc = blockIdx.y;
    const int oc = blockIdx.x * 8 + (threadIdx.x >> 5);
    const int j = (threadIdx.x & 31) * 2;
    const int ic = kc * 64 + j;
    const float* wr = slp_w + (size_t)oc * 1500;
    auto rd = [&](int i) -> float {
        if (i < 600)  return wr[i];
        if (i < 900)  return wr[i] + wr[i + 300];
        if (i < 1200) return wr[i + 300];
        return 0.f;
    };
    __half2 hv;
    hv.x = __float2half_rn(rd(ic));
    hv.y = __float2half_rn(rd(ic + 1));
    int pir = (((j >> 3) ^ (oc & 7)) << 3) | (j & 7);
    *(__half2*)(g_wec + ((size_t)(kc * 512 + oc)) * 64 + pir) = hv;
    if (kc == 0 && blockIdx.x < 5) {
        int idx = blockIdx.x * 256 + threadIdx.x;
        if (idx < 1200) {
            int conv = idx / 300, occ = idx - (idx / 300) * 300;
            const float* b = (conv == 0) ? b1 : (conv == 1) ? b2
                              : (conv == 2) ? b3 : b7;
            g_bconv[idx] = b[occ];
        }
    }
}

// ------------------------- conv GEMM kernel (BM=128, BN=160) ---------------
__global__ __launch_bounds__(512, 1)
void conv_mma_kernel() {
    extern __shared__ char sm[];
    const uint32_t smb = smem_u32(sm);
    const uint32_t mbF = smb + C_NBUF * CH_BUF;          // full barriers
    const uint32_t mbE = mbF + C_NBUF * 8;               // empty barriers
    const int tid = threadIdx.x, lane = tid & 31, wid = tid >> 5;
    const int wm = wid & 3, wn = wid >> 2;               // 4 x 4 warps
    const int quad = lane >> 2, kp2 = (lane & 3) * 2;

    const int conv = 3 - (int)(blockIdx.x >> 1);         // long convs first
    const int oc0  = (blockIdx.x & 1) * 160;
    const int pos0 = blockIdx.y * 128;
    const int bat = pos0 >> 9, l0 = pos0 & 511;
    const int nc = c_nch[conv];                          // 3 per tap
    const int sbase = c_sb[conv];
    const int tb = c_base[conv];
    const bool cut = (oc0 == 160) && (wn == 3);          // cols >=304 dead

    if (tid == 0) {
#pragma unroll
        for (int i = 0; i < C_NBUF; ++i) {
            MBAR_INIT(mbF + i * 8, 1);
            MBAR_INIT(mbE + i * 8, 16);
        }
        FENCE_ASYNC();
    }
    __syncthreads();

    float acc[2][5][4];
#pragma unroll
    for (int mt = 0; mt < 2; ++mt)
#pragma unroll
        for (int nt = 0; nt < 5; ++nt)
#pragma unroll
            for (int e = 0; e < 4; ++e) acc[mt][nt][e] = 0.f;

    // macro-chunk ch: tap = ch/3, part = ch%3; part<2 -> 2 kc-slabs, part==2 -> 1
    auto issue = [&](int ch, int buf) {  // thread 0 only
        int tap = ch / 3, part = ch - tap * 3;
        int kc0 = part * 2;
        int nsub = (part < 2) ? 2 : 1;
        int dlt = c_off[tb + tap];
        uint32_t d = smb + buf * CH_BUF;
        uint32_t m = mbF + buf * 8;
        MBAR_EXPECT_TX(m, (uint32_t)(nsub * 36864));
        for (int s = 0; s < nsub; ++s) {
            const char* a = (const char*)g_xc +
                ((size_t)((bat * 5 + kc0 + s) * 528 + 8 + l0 + dlt)) * 128;
            const char* b = (const char*)g_wcc +
                ((size_t)((sbase + tap * 5 + kc0 + s) * 320 + oc0)) * 128;
            BULK_G2S(d + CH_A + s * 16384, a, 16384, m);
            BULK_G2S(d + CH_B + s * 20480, b, 20480, m);
        }
    };

    if (tid == 0) {
#pragma unroll
        for (int i = 0; i < C_NBUF; ++i)
            if (i < nc) issue(i, i);
    }

    const int hi16 = lane >> 4;
    const int sbB = (lane >> 3) & 1;
    const int rmB = lane & 7;
    const uint32_t aRow  = (uint32_t)(wm * 32 + (lane & 15)) * 128;
    const uint32_t bRow  = (uint32_t)(wn * 40 + (lane & 7) +
                                      ((lane >> 4) & 1) * 8) * 128;
    const uint32_t bRow2 = (uint32_t)(wn * 40 + 32 + (lane & 7)) * 128;

    int buf = 0, ph = 0;
    for (int ch = 0; ch < nc; ++ch) {
        mbar_wait(mbF + buf * 8, ph);
        int tap = ch / 3, part = ch - tap * 3;
        int adj = (8 + c_off[tb + tap]) & 7;             // A swizzle phase
        int rmA = ((lane & 15) + adj) & 7;
        const uint32_t Ab0 = smb + buf * CH_BUF + CH_A;
        const uint32_t Bb0 = smb + buf * CH_BUF + CH_B;
        const int nsub = (part < 2) ? 2 : 1;

        for (int sub = 0; sub < nsub; ++sub) {
            const uint32_t Ab = Ab0 + sub * 16384;
            const uint32_t Bb = Bb0 + sub * 20480;
            auto kstep = [&](int kk) {
                const uint32_t sA = (uint32_t)(((kk * 2 + hi16) ^ rmA) << 4);
                const uint32_t sB = (uint32_t)(((kk * 2 + sbB) ^ rmB) << 4);
                uint32_t ah[2][4];
                LDSM4(ah[0], Ab + aRow + sA);
                LDSM4(ah[1], Ab + aRow + 2048 + sA);
                uint32_t bh4[4];
                LDSM4(bh4, Bb + bRow + sB);
#pragma unroll
                for (int mt = 0; mt < 2; ++mt) {
                    mma16816(acc[mt][0], ah[mt], bh4);
                    mma16816(acc[mt][1], ah[mt], bh4 + 2);
                }
                LDSM4(bh4, Bb + bRow + 2048 + sB);
#pragma unroll
                for (int mt = 0; mt < 2; ++mt) {
                    mma16816(acc[mt][2], ah[mt], bh4);
                    mma16816(acc[mt][3], ah[mt], bh4 + 2);
                }
                if (!cut) {
                    uint32_t bh2[2];
                    LDSM2(bh2, Bb + bRow2 + sB);
#pragma unroll
                    for (int mt = 0; mt < 2; ++mt)
                        mma16816(acc[mt][4], ah[mt], bh2);
                }
            };
            kstep(0);
            kstep(1);
            kstep(2);
            if (part < 2 || nsub == 2) kstep(3);
            else { /* part==2: kc4, ic 304..319 zero pad */ }
            if (part == 2) break;
        }
        // part==2 executes k0..k2 only (k3 = zero pad skipped)

        __syncwarp();
        if (lane == 0) MBAR_ARRIVE(mbE + buf * 8);
        if (tid == 0 && ch + C_NBUF < nc) {
            mbar_wait(mbE + buf * 8, ph);                // all 16 warps done
            issue(ch + C_NBUF, buf);
        }
        if (++buf == C_NBUF) { buf = 0; ph ^= 1; }
    }

    // epilogue: tanh(acc + bias) -> chunked+swizzled fp16 h
#pragma unroll
    for (int mt = 0; mt < 2; ++mt) {
        int r0 = pos0 + wm * 32 + mt * 16 + quad;
#pragma unroll
        for (int nt = 0; nt < 5; ++nt) {
            int col = oc0 + wn * 40 + nt * 8 + kp2;
            if (col >= 300) continue;
            int gc = conv * 300 + col;
            int kc = gc >> 6, j = gc & 63;
            float bi0 = g_bconv[gc], bi1 = g_bconv[gc + 1];
#pragma unroll
            for (int half = 0; half < 2; ++half) {
                int r = r0 + half * 8;
                __half2 hv;
                hv.x = __float2half_rn(tanhf(acc[mt][nt][half * 2 + 0] + bi0));
                hv.y = __float2half_rn(tanhf(acc[mt][nt][half * 2 + 1] + bi1));
                int pir = (((j >> 3) ^ (r & 7)) << 3) | (j & 7);
                *(__half2*)(g_hc + ((size_t)kc * 16384 + r) * 64 + pir) = hv;
            }
        }
    }
}

// ------------------------- SLP GEMM kernel (256 thr, 2 CTAs/SM) ------------
__global__ __launch_bounds__(256, 2)
void slp_mma_kernel(const float* __restrict__ slp_b, float* __restrict__ out) {
    extern __shared__ char sm[];
    const uint32_t smb = smem_u32(sm);
    const uint32_t mbF = smb + S_NBUF * SL_BUF;
    const uint32_t mbE = mbF + S_NBUF * 8;
    const int tid = threadIdx.x, lane = tid & 31, wid = tid >> 5;
    const int wm = wid >> 2, wn = wid & 3;               // 2 x 4 warps
    const int quad = lane >> 2, kp2 = (lane & 3) * 2;
    const int oc0  = blockIdx.x * 128;
    const int pos0 = blockIdx.y * 128;
    const int nc = 19;
    const int rmA = lane & 7;

    if (tid == 0) {
#pragma unroll
        for (int i = 0; i < S_NBUF; ++i) {
            MBAR_INIT(mbF + i * 8, 1);
            MBAR_INIT(mbE + i * 8, 8);
        }
        FENCE_ASYNC();
    }
    __syncthreads();

    float acc[4][4][4];
#pragma unroll
    for (int mt = 0; mt < 4; ++mt)
#pragma unroll
        for (int nt = 0; nt < 4; ++nt)
#pragma unroll
            for (int e = 0; e < 4; ++e) acc[mt][nt][e] = 0.f;

    auto issue = [&](int ch, int buf) {
        const char* a = (const char*)g_hc + ((size_t)ch * 16384 + pos0) * 128;
        const char* b = (const char*)g_wec + ((size_t)ch * 512 + oc0) * 128;
        uint32_t d = smb + buf * SL_BUF;
        uint32_t m = mbF + buf * 8;
        MBAR_EXPECT_TX(m, SL_BUF);
        BULK_G2S(d + SL_A, a, 16384, m);
        BULK_G2S(d + SL_B, b, 16384, m);
    };

    if (tid == 0) { issue(0, 0); issue(1, 1); issue(2, 2); }

    const int hi16 = lane >> 4;
    const int sbB = (lane >> 3) & 1;
    const int rmB = lane & 7;
    const uint32_t aRow  = (uint32_t)(wm * 64 + (lane & 15)) * 128;
    const uint32_t bRow  = (uint32_t)(wn * 32 + (lane & 7) +
                                      ((lane >> 4) & 1) * 8) * 128;

    int buf = 0, ph = 0;
    for (int ch = 0; ch < nc; ++ch) {
        mbar_wait(mbF + buf * 8, (ch / S_NBUF) & 1);
        const uint32_t Ab = smb + buf * SL_BUF + SL_A;
        const uint32_t Bb = smb + buf * SL_BUF + SL_B;

        auto kstep = [&](int kk) {
            const uint32_t sA = (uint32_t)(((kk * 2 + hi16) ^ rmA) << 4);
            const uint32_t sB = (uint32_t)(((kk * 2 + sbB) ^ rmB) << 4);
            uint32_t ah[4][4];
#pragma unroll
            for (int mt = 0; mt < 4; ++mt)
                LDSM4(ah[mt], Ab + aRow + mt * 2048 + sA);
#pragma unroll
            for (int p = 0; p < 2; ++p) {
                uint32_t bh[4];
                LDSM4(bh, Bb + bRow + p * 2048 + sB);
#pragma unroll
                for (int q = 0; q < 2; ++q)
#pragma unroll
                    for (int mt = 0; mt < 4; ++mt)
                        mma16816(acc[mt][p * 2 + q], ah[mt], bh + q * 2);
            }
        };

        kstep(0);
        kstep(1);
        kstep(2);
        if (ch != 18) kstep(3);          // ic 1200..1215 is zero pad: skip
        __syncwarp();
        if (lane == 0) MBAR_ARRIVE(mbE + buf * 8);
        if (tid == 0 && ch + S_NBUF < nc) {
            mbar_wait(mbE + buf * 8, ph);
            issue(ch + S_NBUF, buf);
        }
        if (++buf == S_NBUF) { buf = 0; ph ^= 1; }
    }

#pragma unroll
    for (int mt = 0; mt < 4; ++mt) {
        int r0 = pos0 + wm * 64 + mt * 16 + quad;
#pragma unroll
        for (int nt = 0; nt < 4; ++nt) {
            int col = oc0 + wn * 32 + nt * 8 + kp2;
            float bi0 = slp_b[col], bi1 = slp_b[col + 1];
#pragma unroll
            for (int half = 0; half < 2; ++half) {
                int r = r0 + half * 8;
                float2 v;
                v.x = tanhf(acc[mt][nt][half * 2 + 0] + bi0);
                v.y = tanhf(acc[mt][nt][half * 2 + 1] + bi1);
                *(float2*)(out + (size_t)r * 512 + col) = v;
            }
        }
    }
}

// ------------------------- launch ------------------------------------------
extern "C" void kernel_launch(void* const* d_in, const int* in_sizes, int n_in,
                              void* d_out, int out_size) {
    const float* x     = (const float*)d_in[0];
    const float* w1    = (const float*)d_in[1];
    const float* b1    = (const float*)d_in[2];
    const float* w2    = (const float*)d_in[3];
    const float* b2    = (const float*)d_in[4];
    const float* w3    = (const float*)d_in[5];
    const float* b3    = (const float*)d_in[6];
    const float* w7    = (const float*)d_in[7];
    const float* b7    = (const float*)d_in[8];
    const float* slp_w = (const float*)d_in[9];
    const float* slp_b = (const float*)d_in[10];
    float* out = (float*)d_out;
    (void)b2; (void)b3;

    cudaFuncSetAttribute(conv_mma_kernel, cudaFuncAttributeMaxDynamicSharedMemorySize, CONV_SMEM);
    cudaFuncSetAttribute(slp_mma_kernel,  cudaFuncAttributeMaxDynamicSharedMemorySize, SLP_SMEM);

    prep_x<<<dim3(66, 5, 32), 256>>>(x);
    prep_wc<<<dim3(40, 65), 256>>>(w1, w2, w3, w7);
    prep_we<<<dim3(64, 19), 256>>>(slp_w, b1, b2, b3, b7);

    conv_mma_kernel<<<dim3(8, 128), 512, CONV_SMEM>>>();
    slp_mma_kernel<<<dim3(4, 128), 256, SLP_SMEM>>>(slp_b, out);
}

// round 16
// speedup vs baseline: 1.2830x; 1.1640x over previous
#include <cuda_runtime.h>
#include <cuda_fp16.h>
#include <math.h>
#include <stdint.h>

// ===========================================================================
// TxtNet, fp16 HMMA.16816 (fp32 accum), cp.async.bulk feeds.
// R16: conv + slp FUSED into one 1536-CTA grid with dataflow gating:
//  - blocks 0..1023: conv CTAs, grouped conv3,conv2,conv1,conv0 (long first);
//    each conv bumps a completion counter when its CTAs finish.
//  - blocks 1024..1535: slp CTAs; consume h chunks in dependency-sorted order
//    (conv3's kc first), tid0 gates each bulk issue on the counters.
//  256 thr, 110.7KB smem, 2 CTAs/SM -> slp overlaps the conv tail.
// Conv: 4 GEMMs K=ntap*320 (zero-pad kstep skipped). SLP: 16384x1216x512.
// ===========================================================================

#define P_TOT 16384

// shared smem layout (both roles), 110720 B total
#define CH_A 0
#define CH_B 16384
#define CH_BUF 36864
#define C_NBUF 3
#define SL_A 0
#define SL_B 16384
#define SL_BUF 32768
#define S_NBUF 3
#define MB_OFF (C_NBUF * CH_BUF)              // 110592
#define FUSED_SMEM (MB_OFF + 128)             // 110720

// ------------------------- device scratch (zero-init) ----------------------
__device__ __half g_xc[32 * 5 * 528 * 64];    // [b][kc][row 528 pad][64] sw(row&7)
__device__ __half g_wcc[65 * 320 * 64];       // [slab][oc][64] sw(oc&7)
__device__ __half g_hc[19 * 16384 * 64];      // [kc][pos][64] sw(pos&7)
__device__ __half g_wec[19 * 512 * 64];       // [kc][oc][64] sw(oc&7)
__device__ float g_bconv[1200];
__device__ int   g_cnt[4];                    // per-conv completed CTA count

__constant__ int c_off[13] = {0,  0, 1,  -1, 0, 1,  -3, -2, -1, 0, 1, 2, 3};
__constant__ int c_base[4] = {0, 1, 3, 6};
__constant__ int c_nch[4]  = {5, 10, 15, 35};
__constant__ int c_sb[4]   = {0, 5, 15, 30};
// slp chunk order: conv3's kcs first, boundary kcs last
__constant__ int c_sord[19] = {15, 16, 17, 18, 10, 11, 12, 13,
                               5, 6, 7, 8, 0, 1, 2, 3, 14, 9, 4};

// ------------------------- asm helpers -------------------------------------
__device__ __forceinline__ uint32_t smem_u32(const void* p) {
    uint32_t a;
    asm("{ .reg .u64 t; cvta.to.shared.u64 t, %1; cvt.u32.u64 %0, t; }"
        : "=r"(a) : "l"(p));
    return a;
}
#define BULK_G2S(dst, src, bytes, mbar)                                        \
    asm volatile(                                                              \
        "cp.async.bulk.shared::cluster.global.mbarrier::complete_tx::bytes "   \
        "[%0], [%1], %2, [%3];"                                                \
        :: "r"(dst), "l"(src), "r"(bytes), "r"(mbar) : "memory")
#define MBAR_INIT(a, c) \
    asm volatile("mbarrier.init.shared.b64 [%0], %1;" :: "r"(a), "r"(c) : "memory")
#define MBAR_EXPECT_TX(a, b) \
    asm volatile("mbarrier.arrive.expect_tx.shared.b64 _, [%0], %1;" \
                 :: "r"(a), "r"(b) : "memory")
#define MBAR_ARRIVE(a) \
    asm volatile("mbarrier.arrive.shared.b64 _, [%0];" :: "r"(a) : "memory")
#define FENCE_ASYNC() \
    asm volatile("fence.proxy.async.shared::cta;" ::: "memory")
__device__ __forceinline__ void mbar_wait(uint32_t a, uint32_t ph) {
    asm volatile(
        "{\n .reg .pred P;\nW%=:\n"
        " mbarrier.try_wait.parity.acquire.cta.shared::cta.b64 P, [%0], %1, 0x989680;\n"
        " @!P bra W%=;\n}"
        :: "r"(a), "r"(ph) : "memory");
}
#define LDSM4(R, A) \
    asm volatile("ldmatrix.sync.aligned.m8n8.x4.shared.b16 {%0,%1,%2,%3}, [%4];" \
                 : "=r"((R)[0]), "=r"((R)[1]), "=r"((R)[2]), "=r"((R)[3]) : "r"(A))
#define LDSM2(R, A) \
    asm volatile("ldmatrix.sync.aligned.m8n8.x2.shared.b16 {%0,%1}, [%2];" \
                 : "=r"((R)[0]), "=r"((R)[1]) : "r"(A))

__device__ __forceinline__ void mma16816(float* d, const uint32_t* a,
                                         const uint32_t* b) {
    asm volatile(
        "mma.sync.aligned.m16n8k16.row.col.f32.f16.f16.f32 "
        "{%0,%1,%2,%3}, {%4,%5,%6,%7}, {%8,%9}, {%0,%1,%2,%3};"
        : "+f"(d[0]), "+f"(d[1]), "+f"(d[2]), "+f"(d[3])
        : "r"(a[0]), "r"(a[1]), "r"(a[2]), "r"(a[3]), "r"(b[0]), "r"(b[1]));
}

// ------------------------- prep kernels (div/mod-free) ----------------------
__global__ void prep_x(const float* __restrict__ x) {
    if (blockIdx.x == 0 && blockIdx.y == 0 && blockIdx.z == 0 &&
        threadIdx.x < 4)
        g_cnt[threadIdx.x] = 0;                       // reset stage counters
    const int kc = blockIdx.y, b = blockIdx.z;
    const int r = blockIdx.x * 8 + (threadIdx.x >> 5);
    const int j = (threadIdx.x & 31) * 2;
    int rr = r - 8; rr = rr < 0 ? 0 : (rr > 511 ? 511 : rr);
    const int c = kc * 64 + j;
    const float* xr = x + ((size_t)(b * 512 + rr)) * 300;
    float v0 = (c < 300) ? xr[c] : 0.f;
    float v1 = (c + 1 < 300) ? xr[c + 1] : 0.f;
    __half2 hv; hv.x = __float2half_rn(v0); hv.y = __float2half_rn(v1);
    int pir = (((j >> 3) ^ (r & 7)) << 3) | (j & 7);
    *(__half2*)(g_xc + ((size_t)((b * 5 + kc) * 528 + r)) * 64 + pir) = hv;
}

__global__ void prep_wc(const float* __restrict__ w1, const float* __restrict__ w2,
                        const float* __restrict__ w3, const float* __restrict__ w7) {
    const int s = blockIdx.y;
    const int oc = blockIdx.x * 8 + (threadIdx.x >> 5);
    const int j = (threadIdx.x & 31) * 2;
    int conv = (s < 5) ? 0 : (s < 15) ? 1 : (s < 30) ? 2 : 3;
    int sb = (conv == 0) ? 0 : (conv == 1) ? 5 : (conv == 2) ? 15 : 30;
    int rel = s - sb;
    int tap = rel / 5, kc = rel - (rel / 5) * 5;
    int ic = kc * 64 + j;
    float v0 = 0.f, v1 = 0.f;
    if (oc < 300) {
        const float* w; int K;
        if (conv == 0)      { w = w1; K = 1; }
        else if (conv == 1) { w = w2; K = 2; }
        else if (conv == 2) { w = w3; K = 3; }
        else                { w = w7; K = 7; }
        if (ic < 300)     v0 = w[(oc * 300 + ic) * K + tap];
        if (ic + 1 < 300) v1 = w[(oc * 300 + ic + 1) * K + tap];
    }
    __half2 hv; hv.x = __float2half_rn(v0); hv.y = __float2half_rn(v1);
    int pir = (((j >> 3) ^ (oc & 7)) << 3) | (j & 7);
    *(__half2*)(g_wcc + ((size_t)(s * 320 + oc)) * 64 + pir) = hv;
}

__global__ void prep_we(const float* __restrict__ slp_w,
                        const float* __restrict__ b1, const float* __restrict__ b2,
                        const float* __restrict__ b3, const float* __restrict__ b7) {
    const int kc = blockIdx.y;
    const int oc = blockIdx.x * 8 + (threadIdx.x >> 5);
    const int j = (threadIdx.x & 31) * 2;
    const int ic = kc * 64 + j;
    const float* wr = slp_w + (size_t)oc * 1500;
    auto rd = [&](int i) -> float {
        if (i < 600)  return wr[i];
        if (i < 900)  return wr[i] + wr[i + 300];
        if (i < 1200) return wr[i + 300];
        return 0.f;
    };
    __half2 hv;
    hv.x = __float2half_rn(rd(ic));
    hv.y = __float2half_rn(rd(ic + 1));
    int pir = (((j >> 3) ^ (oc & 7)) << 3) | (j & 7);
    *(__half2*)(g_wec + ((size_t)(kc * 512 + oc)) * 64 + pir) = hv;
    if (kc == 0 && blockIdx.x < 5) {
        int idx = blockIdx.x * 256 + threadIdx.x;
        if (idx < 1200) {
            int conv = idx / 300, occ = idx - (idx / 300) * 300;
            const float* b = (conv == 0) ? b1 : (conv == 1) ? b2
                              : (conv == 2) ? b3 : b7;
            g_bconv[idx] = b[occ];
        }
    }
}

// ------------------------- conv role (BM=128, BN=160, 8 warps) --------------
__device__ __forceinline__ void conv_body(char* sm, int bid) {
    const uint32_t smb = smem_u32(sm);
    const uint32_t mbF = smb + MB_OFF;
    const uint32_t mbE = mbF + C_NBUF * 8;
    const int tid = threadIdx.x, lane = tid & 31, wid = tid >> 5;
    const int wm = wid >> 2, wn = wid & 3;               // 2 x 4 warps
    const int quad = lane >> 2, kp2 = (lane & 3) * 2;

    const int conv = 3 - (bid >> 8);                     // conv3 group first
    const int r256 = bid & 255;
    const int oc0  = (r256 & 1) * 160;
    const int pos0 = (r256 >> 1) * 128;
    const int bat = pos0 >> 9, l0 = pos0 & 511;
    const int nc = c_nch[conv];
    const int sbase = c_sb[conv];
    const int tb = c_base[conv];
    const bool cut = (oc0 == 160) && (wn == 3);

    if (tid == 0) {
#pragma unroll
        for (int i = 0; i < C_NBUF; ++i) {
            MBAR_INIT(mbF + i * 8, 1);
            MBAR_INIT(mbE + i * 8, 8);
        }
        FENCE_ASYNC();
    }
    __syncthreads();

    float acc[4][5][4];
#pragma unroll
    for (int mt = 0; mt < 4; ++mt)
#pragma unroll
        for (int nt = 0; nt < 5; ++nt)
#pragma unroll
            for (int e = 0; e < 4; ++e) acc[mt][nt][e] = 0.f;

    auto issue = [&](int ch, int buf) {  // tid0 only
        int tap = ch / 5, kc = ch - tap * 5;
        int dlt = c_off[tb + tap];
        const char* a = (const char*)g_xc +
            ((size_t)((bat * 5 + kc) * 528 + 8 + l0 + dlt)) * 128;
        const char* b = (const char*)g_wcc +
            ((size_t)((sbase + ch) * 320 + oc0)) * 128;
        uint32_t d = smb + buf * CH_BUF;
        uint32_t m = mbF + buf * 8;
        MBAR_EXPECT_TX(m, CH_BUF);
        BULK_G2S(d + CH_A, a, 16384, m);
        BULK_G2S(d + CH_B, b, 20480, m);
    };

    if (tid == 0) {
        issue(0, 0);
        if (nc > 1) issue(1, 1);
        if (nc > 2) issue(2, 2);
    }

    const int hi16 = lane >> 4;
    const int sbB = (lane >> 3) & 1;
    const int rmB = lane & 7;
    const uint32_t aRow  = (uint32_t)(wm * 64 + (lane & 15)) * 128;
    const uint32_t bRow  = (uint32_t)(wn * 40 + (lane & 7) +
                                      ((lane >> 4) & 1) * 8) * 128;
    const uint32_t bRow2 = (uint32_t)(wn * 40 + 32 + (lane & 7)) * 128;

    int buf = 0, ph = 0;
    for (int ch = 0; ch < nc; ++ch) {
        mbar_wait(mbF + buf * 8, ph);
        int tap = ch / 5;
        int kcl = ch - tap * 5;
        int adj = (8 + c_off[tb + tap]) & 7;
        int rmA = ((lane & 15) + adj) & 7;
        const uint32_t Ab = smb + buf * CH_BUF + CH_A;
        const uint32_t Bb = smb + buf * CH_BUF + CH_B;

        auto kstep = [&](int kk) {
            const uint32_t sA = (uint32_t)(((kk * 2 + hi16) ^ rmA) << 4);
            const uint32_t sB = (uint32_t)(((kk * 2 + sbB) ^ rmB) << 4);
            uint32_t ah[4][4];
#pragma unroll
            for (int mt = 0; mt < 4; ++mt)
                LDSM4(ah[mt], Ab + aRow + mt * 2048 + sA);
            uint32_t bh4[4];
            LDSM4(bh4, Bb + bRow + sB);
#pragma unroll
            for (int mt = 0; mt < 4; ++mt) {
                mma16816(acc[mt][0], ah[mt], bh4);
                mma16816(acc[mt][1], ah[mt], bh4 + 2);
            }
            LDSM4(bh4, Bb + bRow + 2048 + sB);
#pragma unroll
            for (int mt = 0; mt < 4; ++mt) {
                mma16816(acc[mt][2], ah[mt], bh4);
                mma16816(acc[mt][3], ah[mt], bh4 + 2);
            }
            if (!cut) {
                uint32_t bh2[2];
                LDSM2(bh2, Bb + bRow2 + sB);
#pragma unroll
                for (int mt = 0; mt < 4; ++mt)
                    mma16816(acc[mt][4], ah[mt], bh2);
            }
        };

        kstep(0);
        kstep(1);
        kstep(2);
        if (kcl != 4) kstep(3);          // ic 304..319 zero pad: skip
        __syncwarp();
        if (lane == 0) MBAR_ARRIVE(mbE + buf * 8);
        if (tid == 0 && ch + C_NBUF < nc) {
            mbar_wait(mbE + buf * 8, ph);
            issue(ch + C_NBUF, buf);
        }
        if (++buf == C_NBUF) { buf = 0; ph ^= 1; }
    }

    // epilogue: tanh(acc + bias) -> chunked+swizzled fp16 h
#pragma unroll
    for (int mt = 0; mt < 4; ++mt) {
        int r0 = pos0 + wm * 64 + mt * 16 + quad;
#pragma unroll
        for (int nt = 0; nt < 5; ++nt) {
            int col = oc0 + wn * 40 + nt * 8 + kp2;
            if (col >= 300) continue;
            int gc = conv * 300 + col;
            int kc = gc >> 6, j = gc & 63;
            float bi0 = g_bconv[gc], bi1 = g_bconv[gc + 1];
#pragma unroll
            for (int half = 0; half < 2; ++half) {
                int r = r0 + half * 8;
                __half2 hv;
                hv.x = __float2half_rn(tanhf(acc[mt][nt][half * 2 + 0] + bi0));
                hv.y = __float2half_rn(tanhf(acc[mt][nt][half * 2 + 1] + bi1));
                int pir = (((j >> 3) ^ (r & 7)) << 3) | (j & 7);
                *(__half2*)(g_hc + ((size_t)kc * 16384 + r) * 64 + pir) = hv;
            }
        }
    }

    // signal completion of this conv CTA
    __threadfence();
    __syncthreads();
    if (tid == 0) atomicAdd(&g_cnt[conv], 1);
}

// ------------------------- slp role (BM=128, BN=128, 8 warps) ---------------
__device__ __forceinline__ void slp_body(char* sm, int bid,
                                         const float* __restrict__ slp_b,
                                         float* __restrict__ out) {
    const uint32_t smb = smem_u32(sm);
    const uint32_t mbF = smb + MB_OFF;
    const uint32_t mbE = mbF + S_NBUF * 8;
    const int tid = threadIdx.x, lane = tid & 31, wid = tid >> 5;
    const int wm = wid >> 2, wn = wid & 3;
    const int quad = lane >> 2, kp2 = (lane & 3) * 2;
    const int sbid = bid - 1024;
    const int oc0  = (sbid & 3) * 128;
    const int pos0 = (sbid >> 2) * 128;
    const int nc = 19;
    const int rmA = lane & 7;

    if (tid == 0) {
#pragma unroll
        for (int i = 0; i < S_NBUF; ++i) {
            MBAR_INIT(mbF + i * 8, 1);
            MBAR_INIT(mbE + i * 8, 8);
        }
        FENCE_ASYNC();
    }
    __syncthreads();

    float acc[4][4][4];
#pragma unroll
    for (int mt = 0; mt < 4; ++mt)
#pragma unroll
        for (int nt = 0; nt < 4; ++nt)
#pragma unroll
            for (int e = 0; e < 4; ++e) acc[mt][nt][e] = 0.f;

    auto gate = [&](int ch) {            // tid0 only: wait producer convs
        int mask = (ch < 4) ? 1 : (ch == 4) ? 3 : (ch < 9) ? 2
                   : (ch == 9) ? 6 : (ch < 14) ? 4 : (ch == 14) ? 12 : 8;
#pragma unroll
        for (int c = 0; c < 4; ++c)
            if ((mask >> c) & 1)
                while (*((volatile int*)&g_cnt[c]) < 256) __nanosleep(256);
    };

    auto issue = [&](int i, int buf) {   // tid0 only; i = order index
        int ch = c_sord[i];
        gate(ch);
        const char* a = (const char*)g_hc + ((size_t)ch * 16384 + pos0) * 128;
        const char* b = (const char*)g_wec + ((size_t)ch * 512 + oc0) * 128;
        uint32_t d = smb + buf * SL_BUF;
        uint32_t m = mbF + buf * 8;
        MBAR_EXPECT_TX(m, SL_BUF);
        BULK_G2S(d + SL_A, a, 16384, m);
        BULK_G2S(d + SL_B, b, 16384, m);
    };

    if (tid == 0) { issue(0, 0); issue(1, 1); issue(2, 2); }

    const int hi16 = lane >> 4;
    const int sbB = (lane >> 3) & 1;
    const int rmB = lane & 7;
    const uint32_t aRow  = (uint32_t)(wm * 64 + (lane & 15)) * 128;
    const uint32_t bRow  = (uint32_t)(wn * 32 + (lane & 7) +
                                      ((lane >> 4) & 1) * 8) * 128;

    int buf = 0, ph = 0;
    for (int i = 0; i < nc; ++i) {
        int ch = c_sord[i];
        mbar_wait(mbF + buf * 8, (i / S_NBUF) & 1);
        const uint32_t Ab = smb + buf * SL_BUF + SL_A;
        const uint32_t Bb = smb + buf * SL_BUF + SL_B;

        auto kstep = [&](int kk) {
            const uint32_t sA = (uint32_t)(((kk * 2 + hi16) ^ rmA) << 4);
            const uint32_t sB = (uint32_t)(((kk * 2 + sbB) ^ rmB) << 4);
            uint32_t ah[4][4];
#pragma unroll
            for (int mt = 0; mt < 4; ++mt)
                LDSM4(ah[mt], Ab + aRow + mt * 2048 + sA);
#pragma unroll
            for (int p = 0; p < 2; ++p) {
                uint32_t bh[4];
                LDSM4(bh, Bb + bRow + p * 2048 + sB);
#pragma unroll
                for (int q = 0; q < 2; ++q)
#pragma unroll
                    for (int mt = 0; mt < 4; ++mt)
                        mma16816(acc[mt][p * 2 + q], ah[mt], bh + q * 2);
            }
        };

        kstep(0);
        kstep(1);
        kstep(2);
        if (ch != 18) kstep(3);          // ic 1200..1215 zero pad: skip
        __syncwarp();
        if (lane == 0) MBAR_ARRIVE(mbE + buf * 8);
        if (tid == 0 && i + S_NBUF < nc) {
            mbar_wait(mbE + buf * 8, ph);
            issue(i + S_NBUF, buf);
        }
        if (++buf == S_NBUF) { buf = 0; ph ^= 1; }
    }

#pragma unroll
    for (int mt = 0; mt < 4; ++mt) {
        int r0 = pos0 + wm * 64 + mt * 16 + quad;
#pragma unroll
        for (int nt = 0; nt < 4; ++nt) {
            int col = oc0 + wn * 32 + nt * 8 + kp2;
            float bi0 = slp_b[col], bi1 = slp_b[col + 1];
#pragma unroll
            for (int half = 0; half < 2; ++half) {
                int r = r0 + half * 8;
                float2 v;
                v.x = tanhf(acc[mt][nt][half * 2 + 0] + bi0);
                v.y = tanhf(acc[mt][nt][half * 2 + 1] + bi1);
                *(float2*)(out + (size_t)r * 512 + col) = v;
            }
        }
    }
}

// ------------------------- fused kernel ------------------------------------
__global__ __launch_bounds__(256, 2)
void fused_kernel(const float* __restrict__ slp_b, float* __restrict__ out) {
    extern __shared__ char sm[];
    const int bid = blockIdx.x;
    if (bid < 1024) conv_body(sm, bid);
    else            slp_body(sm, bid, slp_b, out);
}

// ------------------------- launch ------------------------------------------
extern "C" void kernel_launch(void* const* d_in, const int* in_sizes, int n_in,
                              void* d_out, int out_size) {
    const float* x     = (const float*)d_in[0];
    const float* w1    = (const float*)d_in[1];
    const float* b1    = (const float*)d_in[2];
    const float* w2    = (const float*)d_in[3];
    const float* b2    = (const float*)d_in[4];
    const float* w3    = (const float*)d_in[5];
    const float* b3    = (const float*)d_in[6];
    const float* w7    = (const float*)d_in[7];
    const float* b7    = (const float*)d_in[8];
    const float* slp_w = (const float*)d_in[9];
    const float* slp_b = (const float*)d_in[10];
    float* out = (float*)d_out;
    (void)b2; (void)b3;

    cudaFuncSetAttribute(fused_kernel,
                         cudaFuncAttributeMaxDynamicSharedMemorySize, FUSED_SMEM);

    prep_x<<<dim3(66, 5, 32), 256>>>(x);
    prep_wc<<<dim3(40, 65), 256>>>(w1, w2, w3, w7);
    prep_we<<<dim3(64, 19), 256>>>(slp_w, b1, b2, b3, b7);

    fused_kernel<<<1536, 256, FUSED_SMEM>>>(slp_b, out);
}